// round 14
// baseline (speedup 1.0000x reference)
#include <cuda_runtime.h>
#include <cuda_bf16.h>
#include <cuda_fp16.h>
#include <cstdint>
#include <math.h>

// ============================================================================
// AnnoCluster on GB300 (plain sm_103 target -> mma.sync HMMA path).
// Encoder GEMM: 3-pass bf16 split (argmax-safe). Decoder: 2-pass fp16 split
// with fused x_q gather epilogue. Dual-stream graph.
// R14: 3-stage decoder pipeline (4-iter mainloop was 25% fill), kf prefetch,
//      one fewer sync per decoder iter.
// ============================================================================

#define BMAX 4096
#define HMAX 128
#define KP1MAX 10240
#define NP2MAX 10112
#define NSPLIT 9
#define NSPLIT_MAX 16
#define XQ_KSPLIT 8

__device__ float g_part[NSPLIT_MAX * BMAX * HMAX];
__device__ float g_xqpart[XQ_KSPLIT * 16 * 10240];
__device__ float g_hq[64 * HMAX];
__device__ float g_xqtab[64 * 10240];
__device__ __nv_bfloat16 g_w1h[HMAX * KP1MAX];
__device__ __nv_bfloat16 g_w1l[HMAX * KP1MAX];
__device__ __half g_w2e[NP2MAX * HMAX];
__device__ __half g_hdh[BMAX * HMAX];
__device__ __half g_hdl[BMAX * HMAX];

// ============================================================================
// helpers
// ============================================================================
__device__ __forceinline__ uint32_t smem_u32(const void* p) {
    uint32_t a;
    asm("{ .reg .u64 t; cvta.to.shared.u64 t, %1; cvt.u32.u64 %0, t; }"
        : "=r"(a) : "l"(p));
    return a;
}
__device__ __forceinline__ void cp16(uint32_t dst, const void* src) {
    asm volatile("cp.async.cg.shared.global [%0], [%1], 16;"
                 :: "r"(dst), "l"(__cvta_generic_to_global(src)) : "memory");
}
#define CP_COMMIT() asm volatile("cp.async.commit_group;" ::: "memory")
#define CP_WAIT(n)  asm volatile("cp.async.wait_group %0;" :: "n"(n) : "memory")

#define LDMX4(r0, r1, r2, r3, a) \
    asm volatile("ldmatrix.sync.aligned.m8n8.x4.shared.b16 {%0,%1,%2,%3}, [%4];" \
                 : "=r"(r0), "=r"(r1), "=r"(r2), "=r"(r3) : "r"(a))

#define MMA_BF16(d, a, b) \
    asm volatile("mma.sync.aligned.m16n8k16.row.col.f32.bf16.bf16.f32 " \
                 "{%0,%1,%2,%3}, {%4,%5,%6,%7}, {%8,%9}, {%0,%1,%2,%3};" \
                 : "+f"((d)[0]), "+f"((d)[1]), "+f"((d)[2]), "+f"((d)[3]) \
                 : "r"((a)[0]), "r"((a)[1]), "r"((a)[2]), "r"((a)[3]), \
                   "r"((b)[0]), "r"((b)[1]))

#define MMA_F16(d, a, b) \
    asm volatile("mma.sync.aligned.m16n8k16.row.col.f32.f16.f16.f32 " \
                 "{%0,%1,%2,%3}, {%4,%5,%6,%7}, {%8,%9}, {%0,%1,%2,%3};" \
                 : "+f"((d)[0]), "+f"((d)[1]), "+f"((d)[2]), "+f"((d)[3]) \
                 : "r"((a)[0]), "r"((a)[1]), "r"((a)[2]), "r"((a)[3]), \
                   "r"((b)[0]), "r"((b)[1]))

__device__ __forceinline__ void sts128(uint32_t a, uint32_t x, uint32_t y,
                                       uint32_t z, uint32_t w) {
    asm volatile("st.shared.v4.b32 [%0], {%1, %2, %3, %4};"
                 :: "r"(a), "r"(x), "r"(y), "r"(z), "r"(w) : "memory");
}

__device__ __forceinline__ uint32_t pack_bf16(__nv_bfloat16 a, __nv_bfloat16 b) {
    return ((uint32_t)__bfloat16_as_ushort(b) << 16) | (uint32_t)__bfloat16_as_ushort(a);
}

#define TROW 80
#define TILE_BYTES (128 * TROW)
#define STAGE_BYTES (4 * TILE_BYTES)
#define SMEM_TOTAL (2 * STAGE_BYTES)       // 81920 (encoder, 2 CTA/SM)
#define STAGE2_BYTES (3 * TILE_BYTES)      // 30720
#define SMEM_TOTAL2 (3 * STAGE2_BYTES)     // 92160 (decoder, 3-stage; > epi 66048)

// ============================================================================
// Encoder GEMM: 3-pass bf16 split, A fp32 (conversion fused), split-K.
// ============================================================================
__global__ __launch_bounds__(256, 2)
void mma_gemm_enc_kernel(const float* __restrict__ Afp,
                         const __nv_bfloat16* __restrict__ Bh,
                         const __nv_bfloat16* __restrict__ Bl,
                         float* __restrict__ C,
                         int lda, int ldb, int ldc, int Nvalid, int Dvalid,
                         int itersPerSplit, int totalIters, long long splitStride)
{
    extern __shared__ char smem[];
    const uint32_t sb = smem_u32(smem);
    const int tid = threadIdx.x;
    const int wid = tid >> 5;
    const int lid = tid & 31;
    const int mBase = blockIdx.y * 128;
    const int nBase = blockIdx.x * 128;
    C += (long long)blockIdx.z * splitStride;
    const int c0 = blockIdx.z * itersPerSplit;
    const int iters = min(itersPerSplit, totalIters - c0);

    auto load_stage_async = [&](int s, int it) {
        const uint32_t dst = sb + (uint32_t)s * STAGE_BYTES;
        const int k0 = (c0 + it) * 32;
#pragma unroll
        for (int t = 0; t < 2; t++) {
            const int id = t * 256 + tid;
            const int r = id >> 2, c = id & 3;
            const uint32_t o = (uint32_t)r * TROW + (uint32_t)c * 16;
            const size_t boff = (size_t)(nBase + r) * ldb + k0 + c * 8;
            cp16(dst + 2 * TILE_BYTES + o, Bh + boff);
            cp16(dst + 3 * TILE_BYTES + o, Bl + boff);
        }
    };

    const int ar_ = tid >> 1;
    const int ah_ = tid & 1;
    float4 pre[4];
    auto ldg_a = [&](int it) {
        const int k0 = (c0 + it) * 32 + ah_ * 16;
        const float* base = Afp + (size_t)(mBase + ar_) * lda;
#pragma unroll
        for (int q = 0; q < 4; q++) {
            const int gk = k0 + q * 4;
            if (gk + 4 <= Dvalid) {
                pre[q] = *(const float4*)(base + gk);
            } else {
                float4 v = make_float4(0.f, 0.f, 0.f, 0.f);
                if (gk < Dvalid) {
                    v.x = base[gk];
                    if (gk + 1 < Dvalid) v.y = base[gk + 1];
                    if (gk + 2 < Dvalid) v.z = base[gk + 2];
                }
                pre[q] = v;
            }
        }
    };
    auto sts_a = [&](int s) {
        const uint32_t dst = sb + (uint32_t)s * STAGE_BYTES +
                             (uint32_t)ar_ * TROW + (uint32_t)ah_ * 32;
        uint32_t hi[4], lo[4];
#pragma unroll
        for (int q = 0; q < 4; q++) {
            const float fx = pre[q].x, fy = pre[q].y, fz = pre[q].z, fw = pre[q].w;
            __nv_bfloat16 h0 = __float2bfloat16(fx), h1 = __float2bfloat16(fy);
            __nv_bfloat16 h2 = __float2bfloat16(fz), h3 = __float2bfloat16(fw);
            hi[q] = pack_bf16(h0, h1);
            __nv_bfloat16 l0 = __float2bfloat16(fx - __bfloat162float(h0));
            __nv_bfloat16 l1 = __float2bfloat16(fy - __bfloat162float(h1));
            lo[q] = pack_bf16(l0, l1);
            __nv_bfloat16 l2 = __float2bfloat16(fz - __bfloat162float(h2));
            __nv_bfloat16 l3 = __float2bfloat16(fw - __bfloat162float(h3));
            pre[q].x = __uint_as_float(pack_bf16(h2, h3));
            pre[q].y = __uint_as_float(pack_bf16(l2, l3));
        }
        sts128(dst,       hi[0], __float_as_uint(pre[0].x), hi[1], __float_as_uint(pre[1].x));
        sts128(dst + 16,  hi[2], __float_as_uint(pre[2].x), hi[3], __float_as_uint(pre[3].x));
        sts128(dst + TILE_BYTES,      lo[0], __float_as_uint(pre[0].y), lo[1], __float_as_uint(pre[1].y));
        sts128(dst + TILE_BYTES + 16, lo[2], __float_as_uint(pre[2].y), lo[3], __float_as_uint(pre[3].y));
    };

    float acc[4][4][4];
#pragma unroll
    for (int i = 0; i < 4; i++)
#pragma unroll
        for (int j = 0; j < 4; j++)
#pragma unroll
            for (int q = 0; q < 4; q++) acc[i][j][q] = 0.f;

    const int wm = (wid >> 2) * 64;
    const int wn = (wid & 3) * 32;
    const int lr = lid >> 2;
    const int lc = lid & 3;

    const int a_row = lid & 15;
    const int a_kh  = (lid >> 4) * 16;
    const int b_grp = lid >> 3;
    const int b_row = lid & 7;
    const int b_nof = (b_grp >> 1) * 8;
    const int b_kh  = (b_grp & 1) * 16;

    load_stage_async(0, 0);
    CP_COMMIT();
    ldg_a(0);

    for (int i = 0; i < iters; i++) {
        const int buf = i & 1;
        sts_a(buf);
        if (i + 1 < iters) { load_stage_async(buf ^ 1, i + 1); CP_COMMIT(); }
        if (i + 1 < iters) ldg_a(i + 1);
        if (i + 1 < iters) { CP_WAIT(1); } else { CP_WAIT(0); }
        __syncthreads();

        const uint32_t base = sb + (uint32_t)buf * STAGE_BYTES;
#pragma unroll
        for (int ks = 0; ks < 2; ks++) {
            const uint32_t ko = (uint32_t)ks * 32;
            uint32_t bh[2][4], bl[2][4];
#pragma unroll
            for (int n2 = 0; n2 < 2; n2++) {
                const uint32_t baddr = base + 2 * TILE_BYTES +
                    (uint32_t)(wn + n2 * 16 + b_nof + b_row) * TROW + ko + b_kh;
                LDMX4(bh[n2][0], bh[n2][1], bh[n2][2], bh[n2][3], baddr);
                LDMX4(bl[n2][0], bl[n2][1], bl[n2][2], bl[n2][3], baddr + TILE_BYTES);
            }
#pragma unroll
            for (int mi = 0; mi < 4; mi++) {
                const uint32_t aaddr = base +
                    (uint32_t)(wm + mi * 16 + a_row) * TROW + ko + a_kh;
                uint32_t a[4], al4[4];
                LDMX4(a[0], a[1], a[2], a[3], aaddr);
                LDMX4(al4[0], al4[1], al4[2], al4[3], aaddr + TILE_BYTES);
#pragma unroll
                for (int n2 = 0; n2 < 2; n2++) {
#pragma unroll
                    for (int w = 0; w < 2; w++) {
                        float* d = acc[mi][n2 * 2 + w];
                        MMA_BF16(d, a,   (bh[n2] + w * 2));
                        MMA_BF16(d, a,   (bl[n2] + w * 2));
                        MMA_BF16(d, al4, (bh[n2] + w * 2));
                    }
                }
            }
        }
        __syncthreads();
    }
    CP_WAIT(0);

    float* stage = (float*)smem;
#pragma unroll
    for (int mi = 0; mi < 4; mi++) {
        const int r0 = wm + mi * 16 + lr;
#pragma unroll
        for (int ni = 0; ni < 4; ni++) {
            const int c = wn + ni * 8 + lc * 2;
            stage[r0 * 129 + c]           = acc[mi][ni][0];
            stage[r0 * 129 + c + 1]       = acc[mi][ni][1];
            stage[(r0 + 8) * 129 + c]     = acc[mi][ni][2];
            stage[(r0 + 8) * 129 + c + 1] = acc[mi][ni][3];
        }
    }
    __syncthreads();
#pragma unroll 4
    for (int idx = tid; idx < 128 * 128; idx += 256) {
        const int r = idx >> 7, c = idx & 127;
        const int n = nBase + c;
        if (n < Nvalid)
            C[(long long)(mBase + r) * ldc + n] = stage[r * 129 + c];
    }
}

// ============================================================================
// Decoder GEMM: 2-pass fp16 split, 3-STAGE cp.async pipeline, fused x_q
// gather epilogue. K = 128 (4 iters).
// ============================================================================
__global__ __launch_bounds__(256, 2)
void mma_gemm_dec_kernel(const __half* __restrict__ Ah,
                         const __half* __restrict__ Al,
                         const __half* __restrict__ Bs,
                         const float* __restrict__ bias,
                         const float* __restrict__ kf,
                         float* __restrict__ C,
                         float* __restrict__ XQ,
                         int lda, int ldb, int ldc, int Nvalid, int iters)
{
    extern __shared__ char smem[];
    __shared__ int kk_s[128];
    const uint32_t sb = smem_u32(smem);
    const int tid = threadIdx.x;
    const int wid = tid >> 5;
    const int lid = tid & 31;
    const int mBase = blockIdx.y * 128;
    const int nBase = blockIdx.x * 128;

    // prefetch per-row cluster ids under the mainloop
    if (tid < 128) kk_s[tid] = (int)kf[mBase + tid];

    auto load_stage_async = [&](int s, int it) {
        const uint32_t dst = sb + (uint32_t)s * STAGE2_BYTES;
        const int k0 = it * 32;
#pragma unroll
        for (int t = 0; t < 2; t++) {
            const int id = t * 256 + tid;
            const int r = id >> 2, c = id & 3;
            const uint32_t o = (uint32_t)r * TROW + (uint32_t)c * 16;
            const size_t aoff = (size_t)(mBase + r) * lda + k0 + c * 8;
            const size_t boff = (size_t)(nBase + r) * ldb + k0 + c * 8;
            cp16(dst + o,                  Ah + aoff);
            cp16(dst + TILE_BYTES + o,     Al + aoff);
            cp16(dst + 2 * TILE_BYTES + o, Bs + boff);
        }
    };

    float acc[4][4][4];
#pragma unroll
    for (int i = 0; i < 4; i++)
#pragma unroll
        for (int j = 0; j < 4; j++)
#pragma unroll
            for (int q = 0; q < 4; q++) acc[i][j][q] = 0.f;

    const int wm = (wid >> 2) * 64;
    const int wn = (wid & 3) * 32;
    const int lr = lid >> 2;
    const int lc = lid & 3;

    const int a_row = lid & 15;
    const int a_kh  = (lid >> 4) * 16;
    const int b_grp = lid >> 3;
    const int b_row = lid & 7;
    const int b_nof = (b_grp >> 1) * 8;
    const int b_kh  = (b_grp & 1) * 16;

    // 3-stage prologue
    load_stage_async(0, 0);
    CP_COMMIT();
    if (1 < iters) { load_stage_async(1, 1); CP_COMMIT(); }

    for (int i = 0; i < iters; i++) {
        if (i + 1 < iters) { CP_WAIT(1); } else { CP_WAIT(0); }
        __syncthreads();
        if (i + 2 < iters) { load_stage_async((i + 2) % 3, i + 2); CP_COMMIT(); }

        const uint32_t base = sb + (uint32_t)(i % 3) * STAGE2_BYTES;
#pragma unroll
        for (int ks = 0; ks < 2; ks++) {
            const uint32_t ko = (uint32_t)ks * 32;
            uint32_t bf[2][4];
#pragma unroll
            for (int n2 = 0; n2 < 2; n2++) {
                const uint32_t baddr = base + 2 * TILE_BYTES +
                    (uint32_t)(wn + n2 * 16 + b_nof + b_row) * TROW + ko + b_kh;
                LDMX4(bf[n2][0], bf[n2][1], bf[n2][2], bf[n2][3], baddr);
            }
#pragma unroll
            for (int mi = 0; mi < 4; mi++) {
                const uint32_t aaddr = base +
                    (uint32_t)(wm + mi * 16 + a_row) * TROW + ko + a_kh;
                uint32_t a[4], al4[4];
                LDMX4(a[0], a[1], a[2], a[3], aaddr);
                LDMX4(al4[0], al4[1], al4[2], al4[3], aaddr + TILE_BYTES);
#pragma unroll
                for (int n2 = 0; n2 < 2; n2++) {
#pragma unroll
                    for (int w = 0; w < 2; w++) {
                        float* d = acc[mi][n2 * 2 + w];
                        MMA_F16(d, a,   (bf[n2] + w * 2));
                        MMA_F16(d, al4, (bf[n2] + w * 2));
                    }
                }
            }
        }
    }

    // all threads done computing before smem reuse as fp32 stage
    __syncthreads();

    float* stage = (float*)smem;
#pragma unroll
    for (int mi = 0; mi < 4; mi++) {
        const int r0 = wm + mi * 16 + lr;
#pragma unroll
        for (int ni = 0; ni < 4; ni++) {
            const int c = wn + ni * 8 + lc * 2;
            stage[r0 * 129 + c]           = acc[mi][ni][0];
            stage[r0 * 129 + c + 1]       = acc[mi][ni][1];
            stage[(r0 + 8) * 129 + c]     = acc[mi][ni][2];
            stage[(r0 + 8) * 129 + c + 1] = acc[mi][ni][3];
        }
    }
    __syncthreads();
#pragma unroll 4
    for (int idx = tid; idx < 128 * 128; idx += 256) {
        const int r = idx >> 7, c = idx & 127;
        const int n = nBase + c;
        if (n < Nvalid) {
            const long long row = (long long)(mBase + r);
            C[row * ldc + n]  = stage[r * 129 + c] + bias[n];
            XQ[row * ldc + n] = g_xqtab[(size_t)kk_s[r] * Nvalid + n];
        }
    }
}

// ============================================================================
// w1 transpose + bf16 hi/lo split, high-ILP 128k x 32n tiles
// ============================================================================
__global__ __launch_bounds__(256)
void transpose_split_kernel(const float* __restrict__ in,
                            __nv_bfloat16* __restrict__ oh,
                            __nv_bfloat16* __restrict__ ol,
                            int K, int N, int Kpad, int Npad)
{
    __shared__ float t[128][33];
    const int tid = threadIdx.x;
    const int k0 = blockIdx.x * 128, n0 = blockIdx.y * 32;

#pragma unroll
    for (int it = 0; it < 16; it++) {
        const int idx = it * 256 + tid;
        const int kk = idx >> 5, nn = idx & 31;
        const int k = k0 + kk, n = n0 + nn;
        t[kk][nn] = (k < K && n < N) ? in[(size_t)k * N + n] : 0.f;
    }
    __syncthreads();

    const int kp = tid & 63;
    const int ng = tid >> 6;
#pragma unroll
    for (int i = 0; i < 8; i++) {
        const int n = n0 + ng + i * 4;
        const int k = k0 + kp * 2;
        if (n < Npad && k < Kpad) {
            const float v0 = t[kp * 2][ng + i * 4];
            const float v1 = t[kp * 2 + 1][ng + i * 4];
            __nv_bfloat16 h0 = __float2bfloat16(v0);
            __nv_bfloat16 h1 = __float2bfloat16(v1);
            __nv_bfloat16 l0 = __float2bfloat16(v0 - __bfloat162float(h0));
            __nv_bfloat16 l1 = __float2bfloat16(v1 - __bfloat162float(h1));
            *(uint32_t*)(oh + (size_t)n * Kpad + k) = pack_bf16(h0, h1);
            *(uint32_t*)(ol + (size_t)n * Kpad + k) = pack_bf16(l0, l1);
        }
    }
}

__global__ void transpose_half_kernel(const float* __restrict__ in,
                                      __half* __restrict__ oh,
                                      int K, int N, int Kpad, int Npad)
{
    __shared__ float t[32][33];
    const int k0 = blockIdx.x * 32, n0 = blockIdx.y * 32;
    for (int i = threadIdx.y; i < 32; i += 8) {
        int k = k0 + i, n = n0 + threadIdx.x;
        t[i][threadIdx.x] = (k < K && n < N) ? in[(size_t)k * N + n] : 0.f;
    }
    __syncthreads();
    for (int i = threadIdx.y; i < 32; i += 8) {
        int n = n0 + i, k = k0 + threadIdx.x;
        if (n < Npad && k < Kpad)
            oh[(size_t)n * Kpad + k] = __float2half(t[threadIdx.x][i]);
    }
}

// ============================================================================
// FUSED post-encoder kernel (h1 + z_e + cluster + decoder-hidden)
// Hardcoded: H=128, Z=32, K=16, splits=NSPLIT. Block 128 thr, 16 rows/block.
// ============================================================================
__global__ __launch_bounds__(128)
void fused_post_kernel(const float* __restrict__ enc_b1,
                       const float* __restrict__ enc_w2,
                       const float* __restrict__ enc_b2,
                       const float* __restrict__ emb,
                       const float* __restrict__ de_w1,
                       const float* __restrict__ de_b1,
                       float* __restrict__ ze_out, float* __restrict__ zq,
                       float* __restrict__ kout, float* __restrict__ zd,
                       float* __restrict__ dp,
                       int B, int H, int Z, int K)
{
    __shared__ float w2s[128 * 32];
    __shared__ float w1s[32 * 128];
    __shared__ float embs[16 * 32];
    __shared__ float hs[16 * 128];
    __shared__ float zes[16 * 32];
    __shared__ float dist[16 * 16];
    __shared__ float ps[16 * 16];
    __shared__ int kbest[16];

    const int tid = threadIdx.x;
    const int b0 = blockIdx.x * 16;
    const int MH = B * H;

    for (int i = tid; i < H * Z; i += 128) w2s[i] = enc_w2[i];
    for (int i = tid; i < Z * H; i += 128) w1s[i] = de_w1[i];
    for (int i = tid; i < K * Z; i += 128) embs[i] = emb[i];

    const float be = enc_b1[tid];
#pragma unroll 4
    for (int r = 0; r < 16; r++) {
        const long long idx = (long long)(b0 + r) * H + tid;
        float s = 0.f;
#pragma unroll
        for (int p = 0; p < NSPLIT; p++) s += g_part[(long long)p * MH + idx];
        hs[r * 128 + tid] = fmaxf(s + be, 0.f);
    }
    __syncthreads();

    {
        const int rr = tid >> 5;
        const int z = tid & 31;
        const float b2v = enc_b2[z];
        float a0 = b2v, a1 = b2v, a2 = b2v, a3 = b2v;
#pragma unroll 8
        for (int k = 0; k < 128; k++) {
            const float w = w2s[k * 32 + z];
            a0 = fmaf(hs[(rr)      * 128 + k], w, a0);
            a1 = fmaf(hs[(rr + 4)  * 128 + k], w, a1);
            a2 = fmaf(hs[(rr + 8)  * 128 + k], w, a2);
            a3 = fmaf(hs[(rr + 12) * 128 + k], w, a3);
        }
        zes[(rr)      * 32 + z] = a0;
        zes[(rr + 4)  * 32 + z] = a1;
        zes[(rr + 8)  * 32 + z] = a2;
        zes[(rr + 12) * 32 + z] = a3;
        ze_out[(size_t)(b0 + rr)      * Z + z] = a0;
        ze_out[(size_t)(b0 + rr + 4)  * Z + z] = a1;
        ze_out[(size_t)(b0 + rr + 8)  * Z + z] = a2;
        ze_out[(size_t)(b0 + rr + 12) * Z + z] = a3;
    }
    __syncthreads();

#pragma unroll
    for (int half = 0; half < 2; half++) {
        const int idx = half * 128 + tid;
        const int r = idx >> 4, k = idx & 15;
        float d = 0.f;
#pragma unroll 8
        for (int z = 0; z < 32; z++) {
            const float df = zes[r * 32 + z] - embs[k * 32 + z];
            d = fmaf(df, df, d);
        }
        dist[r * 16 + k] = d;
        zd[(size_t)(b0 + r) * K + k] = d;
    }
    __syncthreads();

    if (tid < 16) {
        const int r = tid;
        float sum = 0.f;
#pragma unroll
        for (int k = 0; k < 16; k++) {
            const float pk = __powf(1.0f + dist[r * 16 + k] * 0.1f, -5.5f);
            ps[r * 16 + k] = pk;
            sum += pk;
        }
        const float inv = 1.0f / sum;
        int best = 0;
        float bv = -1.f;
#pragma unroll
        for (int k = 0; k < 16; k++) {
            const float v = ps[r * 16 + k] * inv;
            dp[(size_t)(b0 + r) * K + k] = v;
            if (v > bv) { bv = v; best = k; }
        }
        kout[b0 + r] = (float)best;
        kbest[r] = best;
    }
    __syncthreads();

#pragma unroll
    for (int i = 0; i < 4; i++) {
        const int idx = i * 128 + tid;
        const int r = idx >> 5, z = idx & 31;
        zq[(size_t)(b0 + r) * Z + z] = embs[kbest[r] * 32 + z];
    }

    {
        const float bd = de_b1[tid];
        float acc[16];
#pragma unroll
        for (int r = 0; r < 16; r++) acc[r] = bd;
#pragma unroll 4
        for (int z = 0; z < 32; z++) {
            const float w = w1s[z * 128 + tid];
#pragma unroll
            for (int r = 0; r < 16; r++)
                acc[r] = fmaf(zes[r * 32 + z], w, acc[r]);
        }
#pragma unroll
        for (int r = 0; r < 16; r++) {
            const float v = fmaxf(acc[r], 0.f);
            const size_t idx = (size_t)(b0 + r) * H + tid;
            __half hi = __float2half(v);
            g_hdh[idx] = hi;
            g_hdl[idx] = __float2half(v - __half2float(hi));
        }
    }
}

// ============================================================================
// xq-table branch kernels
// ============================================================================
#define MAXZ 64
__global__ void hq_kernel(const float* __restrict__ emb,
                          const float* __restrict__ w1,
                          const float* __restrict__ b1,
                          int K, int Z, int H)
{
    __shared__ float es[64 * MAXZ];
    const int tid = threadIdx.x;
    for (int i = tid; i < K * Z; i += 128) es[i] = emb[i];
    __syncthreads();
    if (tid >= H) return;
    for (int r = 0; r < K; r++) {
        float acc = b1[tid];
        for (int k = 0; k < Z; k++) acc = fmaf(es[r * Z + k], w1[k * H + tid], acc);
        g_hq[r * HMAX + tid] = fmaxf(acc, 0.f);
    }
}

__global__ void xqtab_part_kernel(const float* __restrict__ w2,
                                  int K, int H, int D)
{
    __shared__ float hs[16 * 16];
    const int tid = threadIdx.x;
    const int ks = blockIdx.y;
    const int kw = H / XQ_KSPLIT;
    const int kbase = ks * kw;
    if (tid < K * kw) {
        const int r = tid / kw, kk = tid % kw;
        hs[r * 16 + kk] = g_hq[r * HMAX + kbase + kk];
    }
    __syncthreads();
    const int c = blockIdx.x * 256 + tid;
    if (c >= D) return;
    float acc[16];
#pragma unroll
    for (int r = 0; r < 16; r++) acc[r] = 0.f;
#pragma unroll
    for (int kk = 0; kk < 16; kk++) {
        const float wv = w2[(size_t)(kbase + kk) * D + c];
#pragma unroll
        for (int r = 0; r < 16; r++) acc[r] = fmaf(hs[r * 16 + kk], wv, acc[r]);
    }
    float* part = g_xqpart + (size_t)ks * 16 * D;
#pragma unroll
    for (int r = 0; r < 16; r++)
        if (r < K) part[(size_t)r * D + c] = acc[r];
}

__global__ void xqtab_reduce_kernel(const float* __restrict__ b2, int K, int D)
{
    const int idx = blockIdx.x * blockDim.x + threadIdx.x;
    if (idx >= K * D) return;
    const int r = idx / D;
    const int c = idx - r * D;
    float s = b2[c];
#pragma unroll
    for (int ks = 0; ks < XQ_KSPLIT; ks++)
        s += g_xqpart[(size_t)ks * 16 * D + (size_t)r * D + c];
    g_xqtab[(size_t)r * D + c] = s;
}

// ============================================================================
extern "C" void kernel_launch(void* const* d_in, const int* in_sizes, int n_in,
                              void* d_out, int out_size)
{
    const float* x      = (const float*)d_in[0];
    const float* enc_w1 = (const float*)d_in[1];
    const float* enc_b1 = (const float*)d_in[2];
    const float* enc_w2 = (const float*)d_in[3];
    const float* enc_b2 = (const float*)d_in[4];
    const float* emb    = (const float*)d_in[5];
    const float* de_w1  = (const float*)d_in[6];
    const float* de_b1  = (const float*)d_in[7];
    const float* de_w2  = (const float*)d_in[8];
    const float* de_b2  = (const float*)d_in[9];
    const float* dq_w1  = (const float*)d_in[10];
    const float* dq_b1  = (const float*)d_in[11];
    const float* dq_w2  = (const float*)d_in[12];
    const float* dq_b2  = (const float*)d_in[13];

    const int H = in_sizes[2];
    const int Z = in_sizes[4];
    const int D = in_sizes[1] / H;
    const int B = in_sizes[0] / D;
    const int K = in_sizes[5] / Z;

    const int KP1 = ((D + 255) / 256) * 256;    // 10240
    const int NT2 = (D + 127) / 128;            // 79
    const int NP2 = NT2 * 128;                  // 10112
    const int totalIters = (D + 31) / 32;       // 313
    const int iPS = (totalIters + NSPLIT - 1) / NSPLIT;   // 35

    float* out = (float*)d_out;
    const long long BD = (long long)B * D;
    const long long BZ = (long long)B * Z;
    float* o_xe = out;
    float* o_xq = out + BD;
    float* o_ze = out + 2 * BD;
    float* o_zq = out + 2 * BD + BZ;
    float* o_k  = out + 2 * BD + 2 * BZ;
    float* o_zd = o_k + B;
    float* o_dp = o_zd + (long long)B * K;
    (void)out_size; (void)n_in;

    float* p_part;
    __nv_bfloat16 *p_w1h, *p_w1l;
    __half *p_w2e, *p_hdh, *p_hdl;
    cudaGetSymbolAddress((void**)&p_part, g_part);
    cudaGetSymbolAddress((void**)&p_w1h, g_w1h);
    cudaGetSymbolAddress((void**)&p_w1l, g_w1l);
    cudaGetSymbolAddress((void**)&p_w2e, g_w2e);
    cudaGetSymbolAddress((void**)&p_hdh, g_hdh);
    cudaGetSymbolAddress((void**)&p_hdl, g_hdl);

    cudaFuncSetAttribute(mma_gemm_enc_kernel,
                         cudaFuncAttributeMaxDynamicSharedMemorySize, SMEM_TOTAL);
    cudaFuncSetAttribute(mma_gemm_dec_kernel,
                         cudaFuncAttributeMaxDynamicSharedMemorySize, SMEM_TOTAL2);

    static cudaStream_t s2 = nullptr;
    static cudaEvent_t eFork = nullptr, eB = nullptr;
    if (s2 == nullptr) {
        cudaStreamCreateWithFlags(&s2, cudaStreamNonBlocking);
        cudaEventCreateWithFlags(&eFork, cudaEventDisableTiming);
        cudaEventCreateWithFlags(&eB,    cudaEventDisableTiming);
    }

    // ---- fork side branch ----
    cudaEventRecord(eFork, 0);
    cudaStreamWaitEvent(s2, eFork, 0);

    // ---- stream B: decoder weight transpose + full xq-table chain ----
    {
        dim3 blk(32, 8);
        dim3 g2((H + 31) / 32, (NP2 + 31) / 32);
        transpose_half_kernel<<<g2, blk, 0, s2>>>(de_w2, p_w2e, H, D, H, NP2);
        hq_kernel<<<1, 128, 0, s2>>>(emb, dq_w1, dq_b1, K, Z, H);
        dim3 gx((D + 255) / 256, XQ_KSPLIT);
        xqtab_part_kernel<<<gx, 256, 0, s2>>>(dq_w2, K, H, D);
        xqtab_reduce_kernel<<<(K * D + 255) / 256, 256, 0, s2>>>(dq_b2, K, D);
        cudaEventRecord(eB, s2);
    }

    // ---- stream A: encoder chain ----
    {
        dim3 g1(KP1 / 128, (H + 31) / 32);
        transpose_split_kernel<<<g1, 256>>>(enc_w1, p_w1h, p_w1l, D, H, KP1, H);
    }
    {
        dim3 grid(1, B / 128, NSPLIT);
        mma_gemm_enc_kernel<<<grid, 256, SMEM_TOTAL>>>(
            x, p_w1h, p_w1l, p_part,
            /*lda=*/D, /*ldb=*/KP1, /*ldc=*/H, /*Nvalid=*/H, /*Dvalid=*/D,
            iPS, totalIters, /*splitStride=*/(long long)B * H);
    }
    fused_post_kernel<<<B / 16, 128>>>(enc_b1, enc_w2, enc_b2, emb, de_w1, de_b1,
                                       o_ze, o_zq, o_k, o_zd, o_dp,
                                       B, H, Z, K);

    // ---- stream A: decoder GEMM + fused x_q gather (joins stream B) ----
    cudaStreamWaitEvent(0, eB, 0);
    {
        dim3 grid(NT2, B / 128, 1);
        mma_gemm_dec_kernel<<<grid, 256, SMEM_TOTAL2>>>(
            p_hdh, p_hdl, p_w2e, de_b2, o_k, o_xe, o_xq,
            /*lda=*/H, /*ldb=*/H, /*ldc=*/D, /*Nvalid=*/D, /*iters=*/H / 32);
    }
}

// round 15
// speedup vs baseline: 1.1522x; 1.1522x over previous
#include <cuda_runtime.h>
#include <cuda_bf16.h>
#include <cuda_fp16.h>
#include <cstdint>
#include <math.h>

// ============================================================================
// AnnoCluster on GB300 (plain sm_103 target -> mma.sync HMMA path).
// Encoder GEMM: 3-pass bf16 split (argmax-safe). Decoder: 2-pass fp16 split
// with fused x_q gather epilogue. Dual-stream graph.
// R15: REVERT 3-stage decoder (occupancy fell to 1 CTA/SM at 92KB smem);
//      keep kf prefetch; float4-vectorized GEMM epilogues (132-pad stage).
// ============================================================================

#define BMAX 4096
#define HMAX 128
#define KP1MAX 10240
#define NP2MAX 10112
#define NSPLIT 9
#define NSPLIT_MAX 16
#define XQ_KSPLIT 8

__device__ float g_part[NSPLIT_MAX * BMAX * HMAX];
__device__ float g_xqpart[XQ_KSPLIT * 16 * 10240];
__device__ float g_hq[64 * HMAX];
__device__ float g_xqtab[64 * 10240];
__device__ __nv_bfloat16 g_w1h[HMAX * KP1MAX];
__device__ __nv_bfloat16 g_w1l[HMAX * KP1MAX];
__device__ __half g_w2e[NP2MAX * HMAX];
__device__ __half g_hdh[BMAX * HMAX];
__device__ __half g_hdl[BMAX * HMAX];

// ============================================================================
// helpers
// ============================================================================
__device__ __forceinline__ uint32_t smem_u32(const void* p) {
    uint32_t a;
    asm("{ .reg .u64 t; cvta.to.shared.u64 t, %1; cvt.u32.u64 %0, t; }"
        : "=r"(a) : "l"(p));
    return a;
}
__device__ __forceinline__ void cp16(uint32_t dst, const void* src) {
    asm volatile("cp.async.cg.shared.global [%0], [%1], 16;"
                 :: "r"(dst), "l"(__cvta_generic_to_global(src)) : "memory");
}
#define CP_COMMIT() asm volatile("cp.async.commit_group;" ::: "memory")
#define CP_WAIT(n)  asm volatile("cp.async.wait_group %0;" :: "n"(n) : "memory")

#define LDMX4(r0, r1, r2, r3, a) \
    asm volatile("ldmatrix.sync.aligned.m8n8.x4.shared.b16 {%0,%1,%2,%3}, [%4];" \
                 : "=r"(r0), "=r"(r1), "=r"(r2), "=r"(r3) : "r"(a))

#define MMA_BF16(d, a, b) \
    asm volatile("mma.sync.aligned.m16n8k16.row.col.f32.bf16.bf16.f32 " \
                 "{%0,%1,%2,%3}, {%4,%5,%6,%7}, {%8,%9}, {%0,%1,%2,%3};" \
                 : "+f"((d)[0]), "+f"((d)[1]), "+f"((d)[2]), "+f"((d)[3]) \
                 : "r"((a)[0]), "r"((a)[1]), "r"((a)[2]), "r"((a)[3]), \
                   "r"((b)[0]), "r"((b)[1]))

#define MMA_F16(d, a, b) \
    asm volatile("mma.sync.aligned.m16n8k16.row.col.f32.f16.f16.f32 " \
                 "{%0,%1,%2,%3}, {%4,%5,%6,%7}, {%8,%9}, {%0,%1,%2,%3};" \
                 : "+f"((d)[0]), "+f"((d)[1]), "+f"((d)[2]), "+f"((d)[3]) \
                 : "r"((a)[0]), "r"((a)[1]), "r"((a)[2]), "r"((a)[3]), \
                   "r"((b)[0]), "r"((b)[1]))

__device__ __forceinline__ void sts128(uint32_t a, uint32_t x, uint32_t y,
                                       uint32_t z, uint32_t w) {
    asm volatile("st.shared.v4.b32 [%0], {%1, %2, %3, %4};"
                 :: "r"(a), "r"(x), "r"(y), "r"(z), "r"(w) : "memory");
}

__device__ __forceinline__ uint32_t pack_bf16(__nv_bfloat16 a, __nv_bfloat16 b) {
    return ((uint32_t)__bfloat16_as_ushort(b) << 16) | (uint32_t)__bfloat16_as_ushort(a);
}

#define TROW 80
#define TILE_BYTES (128 * TROW)
#define STAGE_BYTES (4 * TILE_BYTES)
#define SMEM_TOTAL (2 * STAGE_BYTES)       // 81920 (encoder, 2 CTA/SM)
#define STAGE2_BYTES (3 * TILE_BYTES)      // 30720
#define SPAD 132                            // fp32 stage row pad (16B-aligned rows)
#define EPI_BYTES (128 * SPAD * 4)          // 67584
#define SMEM_TOTAL2 (EPI_BYTES)             // > 2*STAGE2_BYTES (61440); 2 CTA/SM ok

// ============================================================================
// Encoder GEMM: 3-pass bf16 split, A fp32 (conversion fused), split-K.
// ============================================================================
__global__ __launch_bounds__(256, 2)
void mma_gemm_enc_kernel(const float* __restrict__ Afp,
                         const __nv_bfloat16* __restrict__ Bh,
                         const __nv_bfloat16* __restrict__ Bl,
                         float* __restrict__ C,
                         int lda, int ldb, int ldc, int Nvalid, int Dvalid,
                         int itersPerSplit, int totalIters, long long splitStride)
{
    extern __shared__ char smem[];
    const uint32_t sb = smem_u32(smem);
    const int tid = threadIdx.x;
    const int wid = tid >> 5;
    const int lid = tid & 31;
    const int mBase = blockIdx.y * 128;
    const int nBase = blockIdx.x * 128;
    C += (long long)blockIdx.z * splitStride;
    const int c0 = blockIdx.z * itersPerSplit;
    const int iters = min(itersPerSplit, totalIters - c0);

    auto load_stage_async = [&](int s, int it) {
        const uint32_t dst = sb + (uint32_t)s * STAGE_BYTES;
        const int k0 = (c0 + it) * 32;
#pragma unroll
        for (int t = 0; t < 2; t++) {
            const int id = t * 256 + tid;
            const int r = id >> 2, c = id & 3;
            const uint32_t o = (uint32_t)r * TROW + (uint32_t)c * 16;
            const size_t boff = (size_t)(nBase + r) * ldb + k0 + c * 8;
            cp16(dst + 2 * TILE_BYTES + o, Bh + boff);
            cp16(dst + 3 * TILE_BYTES + o, Bl + boff);
        }
    };

    const int ar_ = tid >> 1;
    const int ah_ = tid & 1;
    float4 pre[4];
    auto ldg_a = [&](int it) {
        const int k0 = (c0 + it) * 32 + ah_ * 16;
        const float* base = Afp + (size_t)(mBase + ar_) * lda;
#pragma unroll
        for (int q = 0; q < 4; q++) {
            const int gk = k0 + q * 4;
            if (gk + 4 <= Dvalid) {
                pre[q] = *(const float4*)(base + gk);
            } else {
                float4 v = make_float4(0.f, 0.f, 0.f, 0.f);
                if (gk < Dvalid) {
                    v.x = base[gk];
                    if (gk + 1 < Dvalid) v.y = base[gk + 1];
                    if (gk + 2 < Dvalid) v.z = base[gk + 2];
                }
                pre[q] = v;
            }
        }
    };
    auto sts_a = [&](int s) {
        const uint32_t dst = sb + (uint32_t)s * STAGE_BYTES +
                             (uint32_t)ar_ * TROW + (uint32_t)ah_ * 32;
        uint32_t hi[4], lo[4];
#pragma unroll
        for (int q = 0; q < 4; q++) {
            const float fx = pre[q].x, fy = pre[q].y, fz = pre[q].z, fw = pre[q].w;
            __nv_bfloat16 h0 = __float2bfloat16(fx), h1 = __float2bfloat16(fy);
            __nv_bfloat16 h2 = __float2bfloat16(fz), h3 = __float2bfloat16(fw);
            hi[q] = pack_bf16(h0, h1);
            __nv_bfloat16 l0 = __float2bfloat16(fx - __bfloat162float(h0));
            __nv_bfloat16 l1 = __float2bfloat16(fy - __bfloat162float(h1));
            lo[q] = pack_bf16(l0, l1);
            __nv_bfloat16 l2 = __float2bfloat16(fz - __bfloat162float(h2));
            __nv_bfloat16 l3 = __float2bfloat16(fw - __bfloat162float(h3));
            pre[q].x = __uint_as_float(pack_bf16(h2, h3));
            pre[q].y = __uint_as_float(pack_bf16(l2, l3));
        }
        sts128(dst,       hi[0], __float_as_uint(pre[0].x), hi[1], __float_as_uint(pre[1].x));
        sts128(dst + 16,  hi[2], __float_as_uint(pre[2].x), hi[3], __float_as_uint(pre[3].x));
        sts128(dst + TILE_BYTES,      lo[0], __float_as_uint(pre[0].y), lo[1], __float_as_uint(pre[1].y));
        sts128(dst + TILE_BYTES + 16, lo[2], __float_as_uint(pre[2].y), lo[3], __float_as_uint(pre[3].y));
    };

    float acc[4][4][4];
#pragma unroll
    for (int i = 0; i < 4; i++)
#pragma unroll
        for (int j = 0; j < 4; j++)
#pragma unroll
            for (int q = 0; q < 4; q++) acc[i][j][q] = 0.f;

    const int wm = (wid >> 2) * 64;
    const int wn = (wid & 3) * 32;
    const int lr = lid >> 2;
    const int lc = lid & 3;

    const int a_row = lid & 15;
    const int a_kh  = (lid >> 4) * 16;
    const int b_grp = lid >> 3;
    const int b_row = lid & 7;
    const int b_nof = (b_grp >> 1) * 8;
    const int b_kh  = (b_grp & 1) * 16;

    load_stage_async(0, 0);
    CP_COMMIT();
    ldg_a(0);

    for (int i = 0; i < iters; i++) {
        const int buf = i & 1;
        sts_a(buf);
        if (i + 1 < iters) { load_stage_async(buf ^ 1, i + 1); CP_COMMIT(); }
        if (i + 1 < iters) ldg_a(i + 1);
        if (i + 1 < iters) { CP_WAIT(1); } else { CP_WAIT(0); }
        __syncthreads();

        const uint32_t base = sb + (uint32_t)buf * STAGE_BYTES;
#pragma unroll
        for (int ks = 0; ks < 2; ks++) {
            const uint32_t ko = (uint32_t)ks * 32;
            uint32_t bh[2][4], bl[2][4];
#pragma unroll
            for (int n2 = 0; n2 < 2; n2++) {
                const uint32_t baddr = base + 2 * TILE_BYTES +
                    (uint32_t)(wn + n2 * 16 + b_nof + b_row) * TROW + ko + b_kh;
                LDMX4(bh[n2][0], bh[n2][1], bh[n2][2], bh[n2][3], baddr);
                LDMX4(bl[n2][0], bl[n2][1], bl[n2][2], bl[n2][3], baddr + TILE_BYTES);
            }
#pragma unroll
            for (int mi = 0; mi < 4; mi++) {
                const uint32_t aaddr = base +
                    (uint32_t)(wm + mi * 16 + a_row) * TROW + ko + a_kh;
                uint32_t a[4], al4[4];
                LDMX4(a[0], a[1], a[2], a[3], aaddr);
                LDMX4(al4[0], al4[1], al4[2], al4[3], aaddr + TILE_BYTES);
#pragma unroll
                for (int n2 = 0; n2 < 2; n2++) {
#pragma unroll
                    for (int w = 0; w < 2; w++) {
                        float* d = acc[mi][n2 * 2 + w];
                        MMA_BF16(d, a,   (bh[n2] + w * 2));
                        MMA_BF16(d, a,   (bl[n2] + w * 2));
                        MMA_BF16(d, al4, (bh[n2] + w * 2));
                    }
                }
            }
        }
        __syncthreads();
    }
    CP_WAIT(0);

    // epilogue: stage (SPAD-padded) -> float4 global stores
    float* stage = (float*)smem;
#pragma unroll
    for (int mi = 0; mi < 4; mi++) {
        const int r0 = wm + mi * 16 + lr;
#pragma unroll
        for (int ni = 0; ni < 4; ni++) {
            const int c = wn + ni * 8 + lc * 2;
            stage[r0 * SPAD + c]           = acc[mi][ni][0];
            stage[r0 * SPAD + c + 1]       = acc[mi][ni][1];
            stage[(r0 + 8) * SPAD + c]     = acc[mi][ni][2];
            stage[(r0 + 8) * SPAD + c + 1] = acc[mi][ni][3];
        }
    }
    __syncthreads();
#pragma unroll 4
    for (int idx = tid; idx < 128 * 32; idx += 256) {
        const int r = idx >> 5, c = (idx & 31) * 4;
        const int n = nBase + c;
        if (n < Nvalid) {
            const float4 v = *(const float4*)&stage[r * SPAD + c];
            *(float4*)&C[(long long)(mBase + r) * ldc + n] = v;
        }
    }
}

// ============================================================================
// Decoder GEMM: 2-pass fp16 split (R13 2-stage pipeline), kf prefetch,
// fused x_q gather epilogue with float4 stores.
// ============================================================================
__global__ __launch_bounds__(256, 2)
void mma_gemm_dec_kernel(const __half* __restrict__ Ah,
                         const __half* __restrict__ Al,
                         const __half* __restrict__ Bs,
                         const float* __restrict__ bias,
                         const float* __restrict__ kf,
                         float* __restrict__ C,
                         float* __restrict__ XQ,
                         int lda, int ldb, int ldc, int Nvalid, int iters)
{
    extern __shared__ char smem[];
    __shared__ int kk_s[128];
    const uint32_t sb = smem_u32(smem);
    const int tid = threadIdx.x;
    const int wid = tid >> 5;
    const int lid = tid & 31;
    const int mBase = blockIdx.y * 128;
    const int nBase = blockIdx.x * 128;

    // prefetch per-row cluster ids (latency hidden under mainloop)
    if (tid < 128) kk_s[tid] = (int)kf[mBase + tid];

    auto load_stage_async = [&](int s, int it) {
        const uint32_t dst = sb + (uint32_t)s * STAGE2_BYTES;
        const int k0 = it * 32;
#pragma unroll
        for (int t = 0; t < 2; t++) {
            const int id = t * 256 + tid;
            const int r = id >> 2, c = id & 3;
            const uint32_t o = (uint32_t)r * TROW + (uint32_t)c * 16;
            const size_t aoff = (size_t)(mBase + r) * lda + k0 + c * 8;
            const size_t boff = (size_t)(nBase + r) * ldb + k0 + c * 8;
            cp16(dst + o,                  Ah + aoff);
            cp16(dst + TILE_BYTES + o,     Al + aoff);
            cp16(dst + 2 * TILE_BYTES + o, Bs + boff);
        }
    };

    float acc[4][4][4];
#pragma unroll
    for (int i = 0; i < 4; i++)
#pragma unroll
        for (int j = 0; j < 4; j++)
#pragma unroll
            for (int q = 0; q < 4; q++) acc[i][j][q] = 0.f;

    const int wm = (wid >> 2) * 64;
    const int wn = (wid & 3) * 32;
    const int lr = lid >> 2;
    const int lc = lid & 3;

    const int a_row = lid & 15;
    const int a_kh  = (lid >> 4) * 16;
    const int b_grp = lid >> 3;
    const int b_row = lid & 7;
    const int b_nof = (b_grp >> 1) * 8;
    const int b_kh  = (b_grp & 1) * 16;

    load_stage_async(0, 0);
    CP_COMMIT();

    for (int i = 0; i < iters; i++) {
        const int buf = i & 1;
        if (i + 1 < iters) { load_stage_async(buf ^ 1, i + 1); CP_COMMIT(); }
        if (i + 1 < iters) { CP_WAIT(1); } else { CP_WAIT(0); }
        __syncthreads();

        const uint32_t base = sb + (uint32_t)buf * STAGE2_BYTES;
#pragma unroll
        for (int ks = 0; ks < 2; ks++) {
            const uint32_t ko = (uint32_t)ks * 32;
            uint32_t bf[2][4];
#pragma unroll
            for (int n2 = 0; n2 < 2; n2++) {
                const uint32_t baddr = base + 2 * TILE_BYTES +
                    (uint32_t)(wn + n2 * 16 + b_nof + b_row) * TROW + ko + b_kh;
                LDMX4(bf[n2][0], bf[n2][1], bf[n2][2], bf[n2][3], baddr);
            }
#pragma unroll
            for (int mi = 0; mi < 4; mi++) {
                const uint32_t aaddr = base +
                    (uint32_t)(wm + mi * 16 + a_row) * TROW + ko + a_kh;
                uint32_t a[4], al4[4];
                LDMX4(a[0], a[1], a[2], a[3], aaddr);
                LDMX4(al4[0], al4[1], al4[2], al4[3], aaddr + TILE_BYTES);
#pragma unroll
                for (int n2 = 0; n2 < 2; n2++) {
#pragma unroll
                    for (int w = 0; w < 2; w++) {
                        float* d = acc[mi][n2 * 2 + w];
                        MMA_F16(d, a,   (bf[n2] + w * 2));
                        MMA_F16(d, al4, (bf[n2] + w * 2));
                    }
                }
            }
        }
        __syncthreads();
    }
    CP_WAIT(0);

    // epilogue: stage (SPAD-padded) -> float4 stores of x_e and gathered x_q
    float* stage = (float*)smem;
#pragma unroll
    for (int mi = 0; mi < 4; mi++) {
        const int r0 = wm + mi * 16 + lr;
#pragma unroll
        for (int ni = 0; ni < 4; ni++) {
            const int c = wn + ni * 8 + lc * 2;
            stage[r0 * SPAD + c]           = acc[mi][ni][0];
            stage[r0 * SPAD + c + 1]       = acc[mi][ni][1];
            stage[(r0 + 8) * SPAD + c]     = acc[mi][ni][2];
            stage[(r0 + 8) * SPAD + c + 1] = acc[mi][ni][3];
        }
    }
    __syncthreads();
#pragma unroll 4
    for (int idx = tid; idx < 128 * 32; idx += 256) {
        const int r = idx >> 5, c = (idx & 31) * 4;
        const int n = nBase + c;
        if (n < Nvalid) {                           // D % 4 == 0: no straddle
            const long long row = (long long)(mBase + r);
            const float4 s = *(const float4*)&stage[r * SPAD + c];
            const float4 bv = *(const float4*)&bias[n];
            float4 o;
            o.x = s.x + bv.x; o.y = s.y + bv.y;
            o.z = s.z + bv.z; o.w = s.w + bv.w;
            *(float4*)&C[row * ldc + n] = o;
            const float4 t = *(const float4*)&g_xqtab[(size_t)kk_s[r] * Nvalid + n];
            *(float4*)&XQ[row * ldc + n] = t;
        }
    }
}

// ============================================================================
// w1 transpose + bf16 hi/lo split, high-ILP 128k x 32n tiles
// ============================================================================
__global__ __launch_bounds__(256)
void transpose_split_kernel(const float* __restrict__ in,
                            __nv_bfloat16* __restrict__ oh,
                            __nv_bfloat16* __restrict__ ol,
                            int K, int N, int Kpad, int Npad)
{
    __shared__ float t[128][33];
    const int tid = threadIdx.x;
    const int k0 = blockIdx.x * 128, n0 = blockIdx.y * 32;

#pragma unroll
    for (int it = 0; it < 16; it++) {
        const int idx = it * 256 + tid;
        const int kk = idx >> 5, nn = idx & 31;
        const int k = k0 + kk, n = n0 + nn;
        t[kk][nn] = (k < K && n < N) ? in[(size_t)k * N + n] : 0.f;
    }
    __syncthreads();

    const int kp = tid & 63;
    const int ng = tid >> 6;
#pragma unroll
    for (int i = 0; i < 8; i++) {
        const int n = n0 + ng + i * 4;
        const int k = k0 + kp * 2;
        if (n < Npad && k < Kpad) {
            const float v0 = t[kp * 2][ng + i * 4];
            const float v1 = t[kp * 2 + 1][ng + i * 4];
            __nv_bfloat16 h0 = __float2bfloat16(v0);
            __nv_bfloat16 h1 = __float2bfloat16(v1);
            __nv_bfloat16 l0 = __float2bfloat16(v0 - __bfloat162float(h0));
            __nv_bfloat16 l1 = __float2bfloat16(v1 - __bfloat162float(h1));
            *(uint32_t*)(oh + (size_t)n * Kpad + k) = pack_bf16(h0, h1);
            *(uint32_t*)(ol + (size_t)n * Kpad + k) = pack_bf16(l0, l1);
        }
    }
}

__global__ void transpose_half_kernel(const float* __restrict__ in,
                                      __half* __restrict__ oh,
                                      int K, int N, int Kpad, int Npad)
{
    __shared__ float t[32][33];
    const int k0 = blockIdx.x * 32, n0 = blockIdx.y * 32;
    for (int i = threadIdx.y; i < 32; i += 8) {
        int k = k0 + i, n = n0 + threadIdx.x;
        t[i][threadIdx.x] = (k < K && n < N) ? in[(size_t)k * N + n] : 0.f;
    }
    __syncthreads();
    for (int i = threadIdx.y; i < 32; i += 8) {
        int n = n0 + i, k = k0 + threadIdx.x;
        if (n < Npad && k < Kpad)
            oh[(size_t)n * Kpad + k] = __float2half(t[threadIdx.x][i]);
    }
}

// ============================================================================
// FUSED post-encoder kernel (h1 + z_e + cluster + decoder-hidden)
// ============================================================================
__global__ __launch_bounds__(128)
void fused_post_kernel(const float* __restrict__ enc_b1,
                       const float* __restrict__ enc_w2,
                       const float* __restrict__ enc_b2,
                       const float* __restrict__ emb,
                       const float* __restrict__ de_w1,
                       const float* __restrict__ de_b1,
                       float* __restrict__ ze_out, float* __restrict__ zq,
                       float* __restrict__ kout, float* __restrict__ zd,
                       float* __restrict__ dp,
                       int B, int H, int Z, int K)
{
    __shared__ float w2s[128 * 32];
    __shared__ float w1s[32 * 128];
    __shared__ float embs[16 * 32];
    __shared__ float hs[16 * 128];
    __shared__ float zes[16 * 32];
    __shared__ float dist[16 * 16];
    __shared__ float ps[16 * 16];
    __shared__ int kbest[16];

    const int tid = threadIdx.x;
    const int b0 = blockIdx.x * 16;
    const int MH = B * H;

    for (int i = tid; i < H * Z; i += 128) w2s[i] = enc_w2[i];
    for (int i = tid; i < Z * H; i += 128) w1s[i] = de_w1[i];
    for (int i = tid; i < K * Z; i += 128) embs[i] = emb[i];

    const float be = enc_b1[tid];
#pragma unroll 4
    for (int r = 0; r < 16; r++) {
        const long long idx = (long long)(b0 + r) * H + tid;
        float s = 0.f;
#pragma unroll
        for (int p = 0; p < NSPLIT; p++) s += g_part[(long long)p * MH + idx];
        hs[r * 128 + tid] = fmaxf(s + be, 0.f);
    }
    __syncthreads();

    {
        const int rr = tid >> 5;
        const int z = tid & 31;
        const float b2v = enc_b2[z];
        float a0 = b2v, a1 = b2v, a2 = b2v, a3 = b2v;
#pragma unroll 8
        for (int k = 0; k < 128; k++) {
            const float w = w2s[k * 32 + z];
            a0 = fmaf(hs[(rr)      * 128 + k], w, a0);
            a1 = fmaf(hs[(rr + 4)  * 128 + k], w, a1);
            a2 = fmaf(hs[(rr + 8)  * 128 + k], w, a2);
            a3 = fmaf(hs[(rr + 12) * 128 + k], w, a3);
        }
        zes[(rr)      * 32 + z] = a0;
        zes[(rr + 4)  * 32 + z] = a1;
        zes[(rr + 8)  * 32 + z] = a2;
        zes[(rr + 12) * 32 + z] = a3;
        ze_out[(size_t)(b0 + rr)      * Z + z] = a0;
        ze_out[(size_t)(b0 + rr + 4)  * Z + z] = a1;
        ze_out[(size_t)(b0 + rr + 8)  * Z + z] = a2;
        ze_out[(size_t)(b0 + rr + 12) * Z + z] = a3;
    }
    __syncthreads();

#pragma unroll
    for (int half = 0; half < 2; half++) {
        const int idx = half * 128 + tid;
        const int r = idx >> 4, k = idx & 15;
        float d = 0.f;
#pragma unroll 8
        for (int z = 0; z < 32; z++) {
            const float df = zes[r * 32 + z] - embs[k * 32 + z];
            d = fmaf(df, df, d);
        }
        dist[r * 16 + k] = d;
        zd[(size_t)(b0 + r) * K + k] = d;
    }
    __syncthreads();

    if (tid < 16) {
        const int r = tid;
        float sum = 0.f;
#pragma unroll
        for (int k = 0; k < 16; k++) {
            const float pk = __powf(1.0f + dist[r * 16 + k] * 0.1f, -5.5f);
            ps[r * 16 + k] = pk;
            sum += pk;
        }
        const float inv = 1.0f / sum;
        int best = 0;
        float bv = -1.f;
#pragma unroll
        for (int k = 0; k < 16; k++) {
            const float v = ps[r * 16 + k] * inv;
            dp[(size_t)(b0 + r) * K + k] = v;
            if (v > bv) { bv = v; best = k; }
        }
        kout[b0 + r] = (float)best;
        kbest[r] = best;
    }
    __syncthreads();

#pragma unroll
    for (int i = 0; i < 4; i++) {
        const int idx = i * 128 + tid;
        const int r = idx >> 5, z = idx & 31;
        zq[(size_t)(b0 + r) * Z + z] = embs[kbest[r] * 32 + z];
    }

    {
        const float bd = de_b1[tid];
        float acc[16];
#pragma unroll
        for (int r = 0; r < 16; r++) acc[r] = bd;
#pragma unroll 4
        for (int z = 0; z < 32; z++) {
            const float w = w1s[z * 128 + tid];
#pragma unroll
            for (int r = 0; r < 16; r++)
                acc[r] = fmaf(zes[r * 32 + z], w, acc[r]);
        }
#pragma unroll
        for (int r = 0; r < 16; r++) {
            const float v = fmaxf(acc[r], 0.f);
            const size_t idx = (size_t)(b0 + r) * H + tid;
            __half hi = __float2half(v);
            g_hdh[idx] = hi;
            g_hdl[idx] = __float2half(v - __half2float(hi));
        }
    }
}

// ============================================================================
// xq-table branch kernels
// ============================================================================
#define MAXZ 64
__global__ void hq_kernel(const float* __restrict__ emb,
                          const float* __restrict__ w1,
                          const float* __restrict__ b1,
                          int K, int Z, int H)
{
    __shared__ float es[64 * MAXZ];
    const int tid = threadIdx.x;
    for (int i = tid; i < K * Z; i += 128) es[i] = emb[i];
    __syncthreads();
    if (tid >= H) return;
    for (int r = 0; r < K; r++) {
        float acc = b1[tid];
        for (int k = 0; k < Z; k++) acc = fmaf(es[r * Z + k], w1[k * H + tid], acc);
        g_hq[r * HMAX + tid] = fmaxf(acc, 0.f);
    }
}

__global__ void xqtab_part_kernel(const float* __restrict__ w2,
                                  int K, int H, int D)
{
    __shared__ float hs[16 * 16];
    const int tid = threadIdx.x;
    const int ks = blockIdx.y;
    const int kw = H / XQ_KSPLIT;
    const int kbase = ks * kw;
    if (tid < K * kw) {
        const int r = tid / kw, kk = tid % kw;
        hs[r * 16 + kk] = g_hq[r * HMAX + kbase + kk];
    }
    __syncthreads();
    const int c = blockIdx.x * 256 + tid;
    if (c >= D) return;
    float acc[16];
#pragma unroll
    for (int r = 0; r < 16; r++) acc[r] = 0.f;
#pragma unroll
    for (int kk = 0; kk < 16; kk++) {
        const float wv = w2[(size_t)(kbase + kk) * D + c];
#pragma unroll
        for (int r = 0; r < 16; r++) acc[r] = fmaf(hs[r * 16 + kk], wv, acc[r]);
    }
    float* part = g_xqpart + (size_t)ks * 16 * D;
#pragma unroll
    for (int r = 0; r < 16; r++)
        if (r < K) part[(size_t)r * D + c] = acc[r];
}

__global__ void xqtab_reduce_kernel(const float* __restrict__ b2, int K, int D)
{
    const int idx = blockIdx.x * blockDim.x + threadIdx.x;
    if (idx >= K * D) return;
    const int r = idx / D;
    const int c = idx - r * D;
    float s = b2[c];
#pragma unroll
    for (int ks = 0; ks < XQ_KSPLIT; ks++)
        s += g_xqpart[(size_t)ks * 16 * D + (size_t)r * D + c];
    g_xqtab[(size_t)r * D + c] = s;
}

// ============================================================================
extern "C" void kernel_launch(void* const* d_in, const int* in_sizes, int n_in,
                              void* d_out, int out_size)
{
    const float* x      = (const float*)d_in[0];
    const float* enc_w1 = (const float*)d_in[1];
    const float* enc_b1 = (const float*)d_in[2];
    const float* enc_w2 = (const float*)d_in[3];
    const float* enc_b2 = (const float*)d_in[4];
    const float* emb    = (const float*)d_in[5];
    const float* de_w1  = (const float*)d_in[6];
    const float* de_b1  = (const float*)d_in[7];
    const float* de_w2  = (const float*)d_in[8];
    const float* de_b2  = (const float*)d_in[9];
    const float* dq_w1  = (const float*)d_in[10];
    const float* dq_b1  = (const float*)d_in[11];
    const float* dq_w2  = (const float*)d_in[12];
    const float* dq_b2  = (const float*)d_in[13];

    const int H = in_sizes[2];
    const int Z = in_sizes[4];
    const int D = in_sizes[1] / H;
    const int B = in_sizes[0] / D;
    const int K = in_sizes[5] / Z;

    const int KP1 = ((D + 255) / 256) * 256;    // 10240
    const int NT2 = (D + 127) / 128;            // 79
    const int NP2 = NT2 * 128;                  // 10112
    const int totalIters = (D + 31) / 32;       // 313
    const int iPS = (totalIters + NSPLIT - 1) / NSPLIT;   // 35

    float* out = (float*)d_out;
    const long long BD = (long long)B * D;
    const long long BZ = (long long)B * Z;
    float* o_xe = out;
    float* o_xq = out + BD;
    float* o_ze = out + 2 * BD;
    float* o_zq = out + 2 * BD + BZ;
    float* o_k  = out + 2 * BD + 2 * BZ;
    float* o_zd = o_k + B;
    float* o_dp = o_zd + (long long)B * K;
    (void)out_size; (void)n_in;

    float* p_part;
    __nv_bfloat16 *p_w1h, *p_w1l;
    __half *p_w2e, *p_hdh, *p_hdl;
    cudaGetSymbolAddress((void**)&p_part, g_part);
    cudaGetSymbolAddress((void**)&p_w1h, g_w1h);
    cudaGetSymbolAddress((void**)&p_w1l, g_w1l);
    cudaGetSymbolAddress((void**)&p_w2e, g_w2e);
    cudaGetSymbolAddress((void**)&p_hdh, g_hdh);
    cudaGetSymbolAddress((void**)&p_hdl, g_hdl);

    cudaFuncSetAttribute(mma_gemm_enc_kernel,
                         cudaFuncAttributeMaxDynamicSharedMemorySize, SMEM_TOTAL);
    cudaFuncSetAttribute(mma_gemm_dec_kernel,
                         cudaFuncAttributeMaxDynamicSharedMemorySize, SMEM_TOTAL2);

    static cudaStream_t s2 = nullptr;
    static cudaEvent_t eFork = nullptr, eB = nullptr;
    if (s2 == nullptr) {
        cudaStreamCreateWithFlags(&s2, cudaStreamNonBlocking);
        cudaEventCreateWithFlags(&eFork, cudaEventDisableTiming);
        cudaEventCreateWithFlags(&eB,    cudaEventDisableTiming);
    }

    // ---- fork side branch ----
    cudaEventRecord(eFork, 0);
    cudaStreamWaitEvent(s2, eFork, 0);

    // ---- stream B: decoder weight transpose + full xq-table chain ----
    {
        dim3 blk(32, 8);
        dim3 g2((H + 31) / 32, (NP2 + 31) / 32);
        transpose_half_kernel<<<g2, blk, 0, s2>>>(de_w2, p_w2e, H, D, H, NP2);
        hq_kernel<<<1, 128, 0, s2>>>(emb, dq_w1, dq_b1, K, Z, H);
        dim3 gx((D + 255) / 256, XQ_KSPLIT);
        xqtab_part_kernel<<<gx, 256, 0, s2>>>(dq_w2, K, H, D);
        xqtab_reduce_kernel<<<(K * D + 255) / 256, 256, 0, s2>>>(dq_b2, K, D);
        cudaEventRecord(eB, s2);
    }

    // ---- stream A: encoder chain ----
    {
        dim3 g1(KP1 / 128, (H + 31) / 32);
        transpose_split_kernel<<<g1, 256>>>(enc_w1, p_w1h, p_w1l, D, H, KP1, H);
    }
    {
        dim3 grid(1, B / 128, NSPLIT);
        mma_gemm_enc_kernel<<<grid, 256, SMEM_TOTAL>>>(
            x, p_w1h, p_w1l, p_part,
            /*lda=*/D, /*ldb=*/KP1, /*ldc=*/H, /*Nvalid=*/H, /*Dvalid=*/D,
            iPS, totalIters, /*splitStride=*/(long long)B * H);
    }
    fused_post_kernel<<<B / 16, 128>>>(enc_b1, enc_w2, enc_b2, emb, de_w1, de_b1,
                                       o_ze, o_zq, o_k, o_zd, o_dp,
                                       B, H, Z, K);

    // ---- stream A: decoder GEMM + fused x_q gather (joins stream B) ----
    cudaStreamWaitEvent(0, eB, 0);
    {
        dim3 grid(NT2, B / 128, 1);
        mma_gemm_dec_kernel<<<grid, 256, SMEM_TOTAL2>>>(
            p_hdh, p_hdl, p_w2e, de_b2, o_k, o_xe, o_xq,
            /*lda=*/H, /*ldb=*/H, /*ldc=*/D, /*Nvalid=*/D, /*iters=*/H / 32);
    }
}

// round 16
// speedup vs baseline: 1.1578x; 1.0048x over previous
#include <cuda_runtime.h>
#include <cuda_bf16.h>
#include <cuda_fp16.h>
#include <cstdint>
#include <math.h>

// ============================================================================
// AnnoCluster on GB300 (plain sm_103 target -> mma.sync HMMA path).
// Encoder GEMM: 3-pass bf16 split (argmax-safe). Decoder: 2-pass fp16 split
// with fused x_q gather epilogue + float4 stores. Dual-stream graph.
// R16: vectorized fused_post (float4 partial reads, packed uint32 hd writes).
// ============================================================================

#define BMAX 4096
#define HMAX 128
#define KP1MAX 10240
#define NP2MAX 10112
#define NSPLIT 9
#define NSPLIT_MAX 16
#define XQ_KSPLIT 8

__device__ float g_part[NSPLIT_MAX * BMAX * HMAX];
__device__ float g_xqpart[XQ_KSPLIT * 16 * 10240];
__device__ float g_hq[64 * HMAX];
__device__ float g_xqtab[64 * 10240];
__device__ __nv_bfloat16 g_w1h[HMAX * KP1MAX];
__device__ __nv_bfloat16 g_w1l[HMAX * KP1MAX];
__device__ __half g_w2e[NP2MAX * HMAX];
__device__ __half g_hdh[BMAX * HMAX];
__device__ __half g_hdl[BMAX * HMAX];

// ============================================================================
// helpers
// ============================================================================
__device__ __forceinline__ uint32_t smem_u32(const void* p) {
    uint32_t a;
    asm("{ .reg .u64 t; cvta.to.shared.u64 t, %1; cvt.u32.u64 %0, t; }"
        : "=r"(a) : "l"(p));
    return a;
}
__device__ __forceinline__ void cp16(uint32_t dst, const void* src) {
    asm volatile("cp.async.cg.shared.global [%0], [%1], 16;"
                 :: "r"(dst), "l"(__cvta_generic_to_global(src)) : "memory");
}
#define CP_COMMIT() asm volatile("cp.async.commit_group;" ::: "memory")
#define CP_WAIT(n)  asm volatile("cp.async.wait_group %0;" :: "n"(n) : "memory")

#define LDMX4(r0, r1, r2, r3, a) \
    asm volatile("ldmatrix.sync.aligned.m8n8.x4.shared.b16 {%0,%1,%2,%3}, [%4];" \
                 : "=r"(r0), "=r"(r1), "=r"(r2), "=r"(r3) : "r"(a))

#define MMA_BF16(d, a, b) \
    asm volatile("mma.sync.aligned.m16n8k16.row.col.f32.bf16.bf16.f32 " \
                 "{%0,%1,%2,%3}, {%4,%5,%6,%7}, {%8,%9}, {%0,%1,%2,%3};" \
                 : "+f"((d)[0]), "+f"((d)[1]), "+f"((d)[2]), "+f"((d)[3]) \
                 : "r"((a)[0]), "r"((a)[1]), "r"((a)[2]), "r"((a)[3]), \
                   "r"((b)[0]), "r"((b)[1]))

#define MMA_F16(d, a, b) \
    asm volatile("mma.sync.aligned.m16n8k16.row.col.f32.f16.f16.f32 " \
                 "{%0,%1,%2,%3}, {%4,%5,%6,%7}, {%8,%9}, {%0,%1,%2,%3};" \
                 : "+f"((d)[0]), "+f"((d)[1]), "+f"((d)[2]), "+f"((d)[3]) \
                 : "r"((a)[0]), "r"((a)[1]), "r"((a)[2]), "r"((a)[3]), \
                   "r"((b)[0]), "r"((b)[1]))

__device__ __forceinline__ void sts128(uint32_t a, uint32_t x, uint32_t y,
                                       uint32_t z, uint32_t w) {
    asm volatile("st.shared.v4.b32 [%0], {%1, %2, %3, %4};"
                 :: "r"(a), "r"(x), "r"(y), "r"(z), "r"(w) : "memory");
}

__device__ __forceinline__ uint32_t pack_bf16(__nv_bfloat16 a, __nv_bfloat16 b) {
    return ((uint32_t)__bfloat16_as_ushort(b) << 16) | (uint32_t)__bfloat16_as_ushort(a);
}
__device__ __forceinline__ uint32_t pack_half(__half a, __half b) {
    return ((uint32_t)__half_as_ushort(b) << 16) | (uint32_t)__half_as_ushort(a);
}

#define TROW 80
#define TILE_BYTES (128 * TROW)
#define STAGE_BYTES (4 * TILE_BYTES)
#define SMEM_TOTAL (2 * STAGE_BYTES)       // 81920 (encoder, 2 CTA/SM)
#define STAGE2_BYTES (3 * TILE_BYTES)      // 30720
#define SPAD 132                            // fp32 stage row pad (16B-aligned)
#define EPI_BYTES (128 * SPAD * 4)          // 67584
#define SMEM_TOTAL2 (EPI_BYTES)             // 2 CTA/SM ok

// ============================================================================
// Encoder GEMM: 3-pass bf16 split, A fp32 (conversion fused), split-K.
// ============================================================================
__global__ __launch_bounds__(256, 2)
void mma_gemm_enc_kernel(const float* __restrict__ Afp,
                         const __nv_bfloat16* __restrict__ Bh,
                         const __nv_bfloat16* __restrict__ Bl,
                         float* __restrict__ C,
                         int lda, int ldb, int ldc, int Nvalid, int Dvalid,
                         int itersPerSplit, int totalIters, long long splitStride)
{
    extern __shared__ char smem[];
    const uint32_t sb = smem_u32(smem);
    const int tid = threadIdx.x;
    const int wid = tid >> 5;
    const int lid = tid & 31;
    const int mBase = blockIdx.y * 128;
    const int nBase = blockIdx.x * 128;
    C += (long long)blockIdx.z * splitStride;
    const int c0 = blockIdx.z * itersPerSplit;
    const int iters = min(itersPerSplit, totalIters - c0);

    auto load_stage_async = [&](int s, int it) {
        const uint32_t dst = sb + (uint32_t)s * STAGE_BYTES;
        const int k0 = (c0 + it) * 32;
#pragma unroll
        for (int t = 0; t < 2; t++) {
            const int id = t * 256 + tid;
            const int r = id >> 2, c = id & 3;
            const uint32_t o = (uint32_t)r * TROW + (uint32_t)c * 16;
            const size_t boff = (size_t)(nBase + r) * ldb + k0 + c * 8;
            cp16(dst + 2 * TILE_BYTES + o, Bh + boff);
            cp16(dst + 3 * TILE_BYTES + o, Bl + boff);
        }
    };

    const int ar_ = tid >> 1;
    const int ah_ = tid & 1;
    float4 pre[4];
    auto ldg_a = [&](int it) {
        const int k0 = (c0 + it) * 32 + ah_ * 16;
        const float* base = Afp + (size_t)(mBase + ar_) * lda;
#pragma unroll
        for (int q = 0; q < 4; q++) {
            const int gk = k0 + q * 4;
            if (gk + 4 <= Dvalid) {
                pre[q] = *(const float4*)(base + gk);
            } else {
                float4 v = make_float4(0.f, 0.f, 0.f, 0.f);
                if (gk < Dvalid) {
                    v.x = base[gk];
                    if (gk + 1 < Dvalid) v.y = base[gk + 1];
                    if (gk + 2 < Dvalid) v.z = base[gk + 2];
                }
                pre[q] = v;
            }
        }
    };
    auto sts_a = [&](int s) {
        const uint32_t dst = sb + (uint32_t)s * STAGE_BYTES +
                             (uint32_t)ar_ * TROW + (uint32_t)ah_ * 32;
        uint32_t hi[4], lo[4];
#pragma unroll
        for (int q = 0; q < 4; q++) {
            const float fx = pre[q].x, fy = pre[q].y, fz = pre[q].z, fw = pre[q].w;
            __nv_bfloat16 h0 = __float2bfloat16(fx), h1 = __float2bfloat16(fy);
            __nv_bfloat16 h2 = __float2bfloat16(fz), h3 = __float2bfloat16(fw);
            hi[q] = pack_bf16(h0, h1);
            __nv_bfloat16 l0 = __float2bfloat16(fx - __bfloat162float(h0));
            __nv_bfloat16 l1 = __float2bfloat16(fy - __bfloat162float(h1));
            lo[q] = pack_bf16(l0, l1);
            __nv_bfloat16 l2 = __float2bfloat16(fz - __bfloat162float(h2));
            __nv_bfloat16 l3 = __float2bfloat16(fw - __bfloat162float(h3));
            pre[q].x = __uint_as_float(pack_bf16(h2, h3));
            pre[q].y = __uint_as_float(pack_bf16(l2, l3));
        }
        sts128(dst,       hi[0], __float_as_uint(pre[0].x), hi[1], __float_as_uint(pre[1].x));
        sts128(dst + 16,  hi[2], __float_as_uint(pre[2].x), hi[3], __float_as_uint(pre[3].x));
        sts128(dst + TILE_BYTES,      lo[0], __float_as_uint(pre[0].y), lo[1], __float_as_uint(pre[1].y));
        sts128(dst + TILE_BYTES + 16, lo[2], __float_as_uint(pre[2].y), lo[3], __float_as_uint(pre[3].y));
    };

    float acc[4][4][4];
#pragma unroll
    for (int i = 0; i < 4; i++)
#pragma unroll
        for (int j = 0; j < 4; j++)
#pragma unroll
            for (int q = 0; q < 4; q++) acc[i][j][q] = 0.f;

    const int wm = (wid >> 2) * 64;
    const int wn = (wid & 3) * 32;
    const int lr = lid >> 2;
    const int lc = lid & 3;

    const int a_row = lid & 15;
    const int a_kh  = (lid >> 4) * 16;
    const int b_grp = lid >> 3;
    const int b_row = lid & 7;
    const int b_nof = (b_grp >> 1) * 8;
    const int b_kh  = (b_grp & 1) * 16;

    load_stage_async(0, 0);
    CP_COMMIT();
    ldg_a(0);

    for (int i = 0; i < iters; i++) {
        const int buf = i & 1;
        sts_a(buf);
        if (i + 1 < iters) { load_stage_async(buf ^ 1, i + 1); CP_COMMIT(); }
        if (i + 1 < iters) ldg_a(i + 1);
        if (i + 1 < iters) { CP_WAIT(1); } else { CP_WAIT(0); }
        __syncthreads();

        const uint32_t base = sb + (uint32_t)buf * STAGE_BYTES;
#pragma unroll
        for (int ks = 0; ks < 2; ks++) {
            const uint32_t ko = (uint32_t)ks * 32;
            uint32_t bh[2][4], bl[2][4];
#pragma unroll
            for (int n2 = 0; n2 < 2; n2++) {
                const uint32_t baddr = base + 2 * TILE_BYTES +
                    (uint32_t)(wn + n2 * 16 + b_nof + b_row) * TROW + ko + b_kh;
                LDMX4(bh[n2][0], bh[n2][1], bh[n2][2], bh[n2][3], baddr);
                LDMX4(bl[n2][0], bl[n2][1], bl[n2][2], bl[n2][3], baddr + TILE_BYTES);
            }
#pragma unroll
            for (int mi = 0; mi < 4; mi++) {
                const uint32_t aaddr = base +
                    (uint32_t)(wm + mi * 16 + a_row) * TROW + ko + a_kh;
                uint32_t a[4], al4[4];
                LDMX4(a[0], a[1], a[2], a[3], aaddr);
                LDMX4(al4[0], al4[1], al4[2], al4[3], aaddr + TILE_BYTES);
#pragma unroll
                for (int n2 = 0; n2 < 2; n2++) {
#pragma unroll
                    for (int w = 0; w < 2; w++) {
                        float* d = acc[mi][n2 * 2 + w];
                        MMA_BF16(d, a,   (bh[n2] + w * 2));
                        MMA_BF16(d, a,   (bl[n2] + w * 2));
                        MMA_BF16(d, al4, (bh[n2] + w * 2));
                    }
                }
            }
        }
        __syncthreads();
    }
    CP_WAIT(0);

    float* stage = (float*)smem;
#pragma unroll
    for (int mi = 0; mi < 4; mi++) {
        const int r0 = wm + mi * 16 + lr;
#pragma unroll
        for (int ni = 0; ni < 4; ni++) {
            const int c = wn + ni * 8 + lc * 2;
            stage[r0 * SPAD + c]           = acc[mi][ni][0];
            stage[r0 * SPAD + c + 1]       = acc[mi][ni][1];
            stage[(r0 + 8) * SPAD + c]     = acc[mi][ni][2];
            stage[(r0 + 8) * SPAD + c + 1] = acc[mi][ni][3];
        }
    }
    __syncthreads();
#pragma unroll 4
    for (int idx = tid; idx < 128 * 32; idx += 256) {
        const int r = idx >> 5, c = (idx & 31) * 4;
        const int n = nBase + c;
        if (n < Nvalid) {
            const float4 v = *(const float4*)&stage[r * SPAD + c];
            *(float4*)&C[(long long)(mBase + r) * ldc + n] = v;
        }
    }
}

// ============================================================================
// Decoder GEMM: 2-pass fp16 split (2-stage), kf prefetch, fused x_q gather,
// float4 epilogue.
// ============================================================================
__global__ __launch_bounds__(256, 2)
void mma_gemm_dec_kernel(const __half* __restrict__ Ah,
                         const __half* __restrict__ Al,
                         const __half* __restrict__ Bs,
                         const float* __restrict__ bias,
                         const float* __restrict__ kf,
                         float* __restrict__ C,
                         float* __restrict__ XQ,
                         int lda, int ldb, int ldc, int Nvalid, int iters)
{
    extern __shared__ char smem[];
    __shared__ int kk_s[128];
    const uint32_t sb = smem_u32(smem);
    const int tid = threadIdx.x;
    const int wid = tid >> 5;
    const int lid = tid & 31;
    const int mBase = blockIdx.y * 128;
    const int nBase = blockIdx.x * 128;

    if (tid < 128) kk_s[tid] = (int)kf[mBase + tid];

    auto load_stage_async = [&](int s, int it) {
        const uint32_t dst = sb + (uint32_t)s * STAGE2_BYTES;
        const int k0 = it * 32;
#pragma unroll
        for (int t = 0; t < 2; t++) {
            const int id = t * 256 + tid;
            const int r = id >> 2, c = id & 3;
            const uint32_t o = (uint32_t)r * TROW + (uint32_t)c * 16;
            const size_t aoff = (size_t)(mBase + r) * lda + k0 + c * 8;
            const size_t boff = (size_t)(nBase + r) * ldb + k0 + c * 8;
            cp16(dst + o,                  Ah + aoff);
            cp16(dst + TILE_BYTES + o,     Al + aoff);
            cp16(dst + 2 * TILE_BYTES + o, Bs + boff);
        }
    };

    float acc[4][4][4];
#pragma unroll
    for (int i = 0; i < 4; i++)
#pragma unroll
        for (int j = 0; j < 4; j++)
#pragma unroll
            for (int q = 0; q < 4; q++) acc[i][j][q] = 0.f;

    const int wm = (wid >> 2) * 64;
    const int wn = (wid & 3) * 32;
    const int lr = lid >> 2;
    const int lc = lid & 3;

    const int a_row = lid & 15;
    const int a_kh  = (lid >> 4) * 16;
    const int b_grp = lid >> 3;
    const int b_row = lid & 7;
    const int b_nof = (b_grp >> 1) * 8;
    const int b_kh  = (b_grp & 1) * 16;

    load_stage_async(0, 0);
    CP_COMMIT();

    for (int i = 0; i < iters; i++) {
        const int buf = i & 1;
        if (i + 1 < iters) { load_stage_async(buf ^ 1, i + 1); CP_COMMIT(); }
        if (i + 1 < iters) { CP_WAIT(1); } else { CP_WAIT(0); }
        __syncthreads();

        const uint32_t base = sb + (uint32_t)buf * STAGE2_BYTES;
#pragma unroll
        for (int ks = 0; ks < 2; ks++) {
            const uint32_t ko = (uint32_t)ks * 32;
            uint32_t bf[2][4];
#pragma unroll
            for (int n2 = 0; n2 < 2; n2++) {
                const uint32_t baddr = base + 2 * TILE_BYTES +
                    (uint32_t)(wn + n2 * 16 + b_nof + b_row) * TROW + ko + b_kh;
                LDMX4(bf[n2][0], bf[n2][1], bf[n2][2], bf[n2][3], baddr);
            }
#pragma unroll
            for (int mi = 0; mi < 4; mi++) {
                const uint32_t aaddr = base +
                    (uint32_t)(wm + mi * 16 + a_row) * TROW + ko + a_kh;
                uint32_t a[4], al4[4];
                LDMX4(a[0], a[1], a[2], a[3], aaddr);
                LDMX4(al4[0], al4[1], al4[2], al4[3], aaddr + TILE_BYTES);
#pragma unroll
                for (int n2 = 0; n2 < 2; n2++) {
#pragma unroll
                    for (int w = 0; w < 2; w++) {
                        float* d = acc[mi][n2 * 2 + w];
                        MMA_F16(d, a,   (bf[n2] + w * 2));
                        MMA_F16(d, al4, (bf[n2] + w * 2));
                    }
                }
            }
        }
        __syncthreads();
    }
    CP_WAIT(0);

    float* stage = (float*)smem;
#pragma unroll
    for (int mi = 0; mi < 4; mi++) {
        const int r0 = wm + mi * 16 + lr;
#pragma unroll
        for (int ni = 0; ni < 4; ni++) {
            const int c = wn + ni * 8 + lc * 2;
            stage[r0 * SPAD + c]           = acc[mi][ni][0];
            stage[r0 * SPAD + c + 1]       = acc[mi][ni][1];
            stage[(r0 + 8) * SPAD + c]     = acc[mi][ni][2];
            stage[(r0 + 8) * SPAD + c + 1] = acc[mi][ni][3];
        }
    }
    __syncthreads();
#pragma unroll 4
    for (int idx = tid; idx < 128 * 32; idx += 256) {
        const int r = idx >> 5, c = (idx & 31) * 4;
        const int n = nBase + c;
        if (n < Nvalid) {                           // D % 4 == 0: no straddle
            const long long row = (long long)(mBase + r);
            const float4 s = *(const float4*)&stage[r * SPAD + c];
            const float4 bv = *(const float4*)&bias[n];
            float4 o;
            o.x = s.x + bv.x; o.y = s.y + bv.y;
            o.z = s.z + bv.z; o.w = s.w + bv.w;
            *(float4*)&C[row * ldc + n] = o;
            const float4 t = *(const float4*)&g_xqtab[(size_t)kk_s[r] * Nvalid + n];
            *(float4*)&XQ[row * ldc + n] = t;
        }
    }
}

// ============================================================================
// w1 transpose + bf16 hi/lo split, high-ILP 128k x 32n tiles
// ============================================================================
__global__ __launch_bounds__(256)
void transpose_split_kernel(const float* __restrict__ in,
                            __nv_bfloat16* __restrict__ oh,
                            __nv_bfloat16* __restrict__ ol,
                            int K, int N, int Kpad, int Npad)
{
    __shared__ float t[128][33];
    const int tid = threadIdx.x;
    const int k0 = blockIdx.x * 128, n0 = blockIdx.y * 32;

#pragma unroll
    for (int it = 0; it < 16; it++) {
        const int idx = it * 256 + tid;
        const int kk = idx >> 5, nn = idx & 31;
        const int k = k0 + kk, n = n0 + nn;
        t[kk][nn] = (k < K && n < N) ? in[(size_t)k * N + n] : 0.f;
    }
    __syncthreads();

    const int kp = tid & 63;
    const int ng = tid >> 6;
#pragma unroll
    for (int i = 0; i < 8; i++) {
        const int n = n0 + ng + i * 4;
        const int k = k0 + kp * 2;
        if (n < Npad && k < Kpad) {
            const float v0 = t[kp * 2][ng + i * 4];
            const float v1 = t[kp * 2 + 1][ng + i * 4];
            __nv_bfloat16 h0 = __float2bfloat16(v0);
            __nv_bfloat16 h1 = __float2bfloat16(v1);
            __nv_bfloat16 l0 = __float2bfloat16(v0 - __bfloat162float(h0));
            __nv_bfloat16 l1 = __float2bfloat16(v1 - __bfloat162float(h1));
            *(uint32_t*)(oh + (size_t)n * Kpad + k) = pack_bf16(h0, h1);
            *(uint32_t*)(ol + (size_t)n * Kpad + k) = pack_bf16(l0, l1);
        }
    }
}

__global__ void transpose_half_kernel(const float* __restrict__ in,
                                      __half* __restrict__ oh,
                                      int K, int N, int Kpad, int Npad)
{
    __shared__ float t[32][33];
    const int k0 = blockIdx.x * 32, n0 = blockIdx.y * 32;
    for (int i = threadIdx.y; i < 32; i += 8) {
        int k = k0 + i, n = n0 + threadIdx.x;
        t[i][threadIdx.x] = (k < K && n < N) ? in[(size_t)k * N + n] : 0.f;
    }
    __syncthreads();
    for (int i = threadIdx.y; i < 32; i += 8) {
        int n = n0 + i, k = k0 + threadIdx.x;
        if (n < Npad && k < Kpad)
            oh[(size_t)n * Kpad + k] = __float2half(t[threadIdx.x][i]);
    }
}

// ============================================================================
// FUSED post-encoder kernel (h1 + z_e + cluster + decoder-hidden)
// R16: float4 partial reads (phase 1), packed uint32 hidden writes (phase 4).
// Hardcoded: H=128, Z=32, K=16. Block 128 thr, 16 rows/block.
// ============================================================================
__global__ __launch_bounds__(128)
void fused_post_kernel(const float* __restrict__ enc_b1,
                       const float* __restrict__ enc_w2,
                       const float* __restrict__ enc_b2,
                       const float* __restrict__ emb,
                       const float* __restrict__ de_w1,
                       const float* __restrict__ de_b1,
                       float* __restrict__ ze_out, float* __restrict__ zq,
                       float* __restrict__ kout, float* __restrict__ zd,
                       float* __restrict__ dp,
                       int B, int H, int Z, int K)
{
    __shared__ float w2s[128 * 32];
    __shared__ float w1s[32 * 128];
    __shared__ float embs[16 * 32];
    __shared__ float hs[16 * 128];      // h1 (phase 1-2); reused as hd staging (phase 4)
    __shared__ float zes[16 * 32];
    __shared__ float dist[16 * 16];
    __shared__ float ps[16 * 16];
    __shared__ int kbest[16];

    const int tid = threadIdx.x;
    const int b0 = blockIdx.x * 16;
    const int MH = B * H;

    for (int i = tid; i < H * Z; i += 128) w2s[i] = enc_w2[i];
    for (int i = tid; i < Z * H; i += 128) w1s[i] = de_w1[i];
    for (int i = tid; i < K * Z; i += 128) embs[i] = emb[i];

    // phase 1: h1 -- float4 reads of partials (same per-element sum order)
    {
        const int q = tid & 31;            // h quad: h = 4q..4q+3
        const int rg = tid >> 5;           // rows rg, rg+4, rg+8, rg+12
        const float4 b4 = *(const float4*)&enc_b1[q * 4];
#pragma unroll
        for (int rb = 0; rb < 4; rb++) {
            const int r = rg + rb * 4;
            const long long base = (long long)(b0 + r) * H + q * 4;
            float4 s = make_float4(0.f, 0.f, 0.f, 0.f);
#pragma unroll
            for (int p = 0; p < NSPLIT; p++) {
                const float4 v = *(const float4*)&g_part[(long long)p * MH + base];
                s.x += v.x; s.y += v.y; s.z += v.z; s.w += v.w;
            }
            float4 h;
            h.x = fmaxf(s.x + b4.x, 0.f);
            h.y = fmaxf(s.y + b4.y, 0.f);
            h.z = fmaxf(s.z + b4.z, 0.f);
            h.w = fmaxf(s.w + b4.w, 0.f);
            *(float4*)&hs[r * 128 + q * 4] = h;
        }
    }
    __syncthreads();

    // phase 2: z_e -- 4 rows/thread, parallel accumulators
    {
        const int rr = tid >> 5;
        const int z = tid & 31;
        const float b2v = enc_b2[z];
        float a0 = b2v, a1 = b2v, a2 = b2v, a3 = b2v;
#pragma unroll 8
        for (int k = 0; k < 128; k++) {
            const float w = w2s[k * 32 + z];
            a0 = fmaf(hs[(rr)      * 128 + k], w, a0);
            a1 = fmaf(hs[(rr + 4)  * 128 + k], w, a1);
            a2 = fmaf(hs[(rr + 8)  * 128 + k], w, a2);
            a3 = fmaf(hs[(rr + 12) * 128 + k], w, a3);
        }
        zes[(rr)      * 32 + z] = a0;
        zes[(rr + 4)  * 32 + z] = a1;
        zes[(rr + 8)  * 32 + z] = a2;
        zes[(rr + 12) * 32 + z] = a3;
        ze_out[(size_t)(b0 + rr)      * Z + z] = a0;
        ze_out[(size_t)(b0 + rr + 4)  * Z + z] = a1;
        ze_out[(size_t)(b0 + rr + 8)  * Z + z] = a2;
        ze_out[(size_t)(b0 + rr + 12) * Z + z] = a3;
    }
    __syncthreads();

    // phase 3a: distances
#pragma unroll
    for (int half = 0; half < 2; half++) {
        const int idx = half * 128 + tid;
        const int r = idx >> 4, k = idx & 15;
        float d = 0.f;
#pragma unroll 8
        for (int z = 0; z < 32; z++) {
            const float df = zes[r * 32 + z] - embs[k * 32 + z];
            d = fmaf(df, df, d);
        }
        dist[r * 16 + k] = d;
        zd[(size_t)(b0 + r) * K + k] = d;
    }
    __syncthreads();

    // phase 3b: t-kernel + normalize + argmax
    if (tid < 16) {
        const int r = tid;
        float sum = 0.f;
#pragma unroll
        for (int k = 0; k < 16; k++) {
            const float pk = __powf(1.0f + dist[r * 16 + k] * 0.1f, -5.5f);
            ps[r * 16 + k] = pk;
            sum += pk;
        }
        const float inv = 1.0f / sum;
        int best = 0;
        float bv = -1.f;
#pragma unroll
        for (int k = 0; k < 16; k++) {
            const float v = ps[r * 16 + k] * inv;
            dp[(size_t)(b0 + r) * K + k] = v;
            if (v > bv) { bv = v; best = k; }
        }
        kout[b0 + r] = (float)best;
        kbest[r] = best;
    }
    __syncthreads();

    // phase 3c: z_q gather
#pragma unroll
    for (int i = 0; i < 4; i++) {
        const int idx = i * 128 + tid;
        const int r = idx >> 5, z = idx & 31;
        zq[(size_t)(b0 + r) * Z + z] = embs[kbest[r] * 32 + z];
    }

    // phase 4: decoder hidden (16 parallel accumulators), staged packed writes
    {
        const float bd = de_b1[tid];
        float acc[16];
#pragma unroll
        for (int r = 0; r < 16; r++) acc[r] = bd;
#pragma unroll 4
        for (int z = 0; z < 32; z++) {
            const float w = w1s[z * 128 + tid];
#pragma unroll
            for (int r = 0; r < 16; r++)
                acc[r] = fmaf(zes[r * 32 + z], w, acc[r]);
        }
        // stage hi/lo halves in smem (hs is dead after phase 2)
        __half* sh_hi = (__half*)hs;             // 16*128 halves = 4KB
        __half* sh_lo = (__half*)(hs + 1024);    // next 4KB
#pragma unroll
        for (int r = 0; r < 16; r++) {
            const float v = fmaxf(acc[r], 0.f);
            const __half hi = __float2half(v);
            sh_hi[r * 128 + tid] = hi;
            sh_lo[r * 128 + tid] = __float2half(v - __half2float(hi));
        }
        __syncthreads();
        // packed uint32 copy-out (2 halves per store)
#pragma unroll
        for (int it = 0; it < 8; it++) {
            const int idx = it * 128 + tid;      // 0..1023
            const int r = idx >> 6, hp = (idx & 63) * 2;
            const uint32_t a = *(const uint32_t*)&sh_hi[r * 128 + hp];
            const uint32_t b = *(const uint32_t*)&sh_lo[r * 128 + hp];
            *(uint32_t*)&g_hdh[(size_t)(b0 + r) * 128 + hp] = a;
            *(uint32_t*)&g_hdl[(size_t)(b0 + r) * 128 + hp] = b;
        }
    }
}

// ============================================================================
// xq-table branch kernels
// ============================================================================
#define MAXZ 64
__global__ void hq_kernel(const float* __restrict__ emb,
                          const float* __restrict__ w1,
                          const float* __restrict__ b1,
                          int K, int Z, int H)
{
    __shared__ float es[64 * MAXZ];
    const int tid = threadIdx.x;
    for (int i = tid; i < K * Z; i += 128) es[i] = emb[i];
    __syncthreads();
    if (tid >= H) return;
    for (int r = 0; r < K; r++) {
        float acc = b1[tid];
        for (int k = 0; k < Z; k++) acc = fmaf(es[r * Z + k], w1[k * H + tid], acc);
        g_hq[r * HMAX + tid] = fmaxf(acc, 0.f);
    }
}

__global__ void xqtab_part_kernel(const float* __restrict__ w2,
                                  int K, int H, int D)
{
    __shared__ float hs[16 * 16];
    const int tid = threadIdx.x;
    const int ks = blockIdx.y;
    const int kw = H / XQ_KSPLIT;
    const int kbase = ks * kw;
    if (tid < K * kw) {
        const int r = tid / kw, kk = tid % kw;
        hs[r * 16 + kk] = g_hq[r * HMAX + kbase + kk];
    }
    __syncthreads();
    const int c = blockIdx.x * 256 + tid;
    if (c >= D) return;
    float acc[16];
#pragma unroll
    for (int r = 0; r < 16; r++) acc[r] = 0.f;
#pragma unroll
    for (int kk = 0; kk < 16; kk++) {
        const float wv = w2[(size_t)(kbase + kk) * D + c];
#pragma unroll
        for (int r = 0; r < 16; r++) acc[r] = fmaf(hs[r * 16 + kk], wv, acc[r]);
    }
    float* part = g_xqpart + (size_t)ks * 16 * D;
#pragma unroll
    for (int r = 0; r < 16; r++)
        if (r < K) part[(size_t)r * D + c] = acc[r];
}

__global__ void xqtab_reduce_kernel(const float* __restrict__ b2, int K, int D)
{
    const int idx = blockIdx.x * blockDim.x + threadIdx.x;
    if (idx >= K * D) return;
    const int r = idx / D;
    const int c = idx - r * D;
    float s = b2[c];
#pragma unroll
    for (int ks = 0; ks < XQ_KSPLIT; ks++)
        s += g_xqpart[(size_t)ks * 16 * D + (size_t)r * D + c];
    g_xqtab[(size_t)r * D + c] = s;
}

// ============================================================================
extern "C" void kernel_launch(void* const* d_in, const int* in_sizes, int n_in,
                              void* d_out, int out_size)
{
    const float* x      = (const float*)d_in[0];
    const float* enc_w1 = (const float*)d_in[1];
    const float* enc_b1 = (const float*)d_in[2];
    const float* enc_w2 = (const float*)d_in[3];
    const float* enc_b2 = (const float*)d_in[4];
    const float* emb    = (const float*)d_in[5];
    const float* de_w1  = (const float*)d_in[6];
    const float* de_b1  = (const float*)d_in[7];
    const float* de_w2  = (const float*)d_in[8];
    const float* de_b2  = (const float*)d_in[9];
    const float* dq_w1  = (const float*)d_in[10];
    const float* dq_b1  = (const float*)d_in[11];
    const float* dq_w2  = (const float*)d_in[12];
    const float* dq_b2  = (const float*)d_in[13];

    const int H = in_sizes[2];
    const int Z = in_sizes[4];
    const int D = in_sizes[1] / H;
    const int B = in_sizes[0] / D;
    const int K = in_sizes[5] / Z;

    const int KP1 = ((D + 255) / 256) * 256;    // 10240
    const int NT2 = (D + 127) / 128;            // 79
    const int NP2 = NT2 * 128;                  // 10112
    const int totalIters = (D + 31) / 32;       // 313
    const int iPS = (totalIters + NSPLIT - 1) / NSPLIT;   // 35

    float* out = (float*)d_out;
    const long long BD = (long long)B * D;
    const long long BZ = (long long)B * Z;
    float* o_xe = out;
    float* o_xq = out + BD;
    float* o_ze = out + 2 * BD;
    float* o_zq = out + 2 * BD + BZ;
    float* o_k  = out + 2 * BD + 2 * BZ;
    float* o_zd = o_k + B;
    float* o_dp = o_zd + (long long)B * K;
    (void)out_size; (void)n_in;

    float* p_part;
    __nv_bfloat16 *p_w1h, *p_w1l;
    __half *p_w2e, *p_hdh, *p_hdl;
    cudaGetSymbolAddress((void**)&p_part, g_part);
    cudaGetSymbolAddress((void**)&p_w1h, g_w1h);
    cudaGetSymbolAddress((void**)&p_w1l, g_w1l);
    cudaGetSymbolAddress((void**)&p_w2e, g_w2e);
    cudaGetSymbolAddress((void**)&p_hdh, g_hdh);
    cudaGetSymbolAddress((void**)&p_hdl, g_hdl);

    cudaFuncSetAttribute(mma_gemm_enc_kernel,
                         cudaFuncAttributeMaxDynamicSharedMemorySize, SMEM_TOTAL);
    cudaFuncSetAttribute(mma_gemm_dec_kernel,
                         cudaFuncAttributeMaxDynamicSharedMemorySize, SMEM_TOTAL2);

    static cudaStream_t s2 = nullptr;
    static cudaEvent_t eFork = nullptr, eB = nullptr;
    if (s2 == nullptr) {
        cudaStreamCreateWithFlags(&s2, cudaStreamNonBlocking);
        cudaEventCreateWithFlags(&eFork, cudaEventDisableTiming);
        cudaEventCreateWithFlags(&eB,    cudaEventDisableTiming);
    }

    // ---- fork side branch ----
    cudaEventRecord(eFork, 0);
    cudaStreamWaitEvent(s2, eFork, 0);

    // ---- stream B: decoder weight transpose + full xq-table chain ----
    {
        dim3 blk(32, 8);
        dim3 g2((H + 31) / 32, (NP2 + 31) / 32);
        transpose_half_kernel<<<g2, blk, 0, s2>>>(de_w2, p_w2e, H, D, H, NP2);
        hq_kernel<<<1, 128, 0, s2>>>(emb, dq_w1, dq_b1, K, Z, H);
        dim3 gx((D + 255) / 256, XQ_KSPLIT);
        xqtab_part_kernel<<<gx, 256, 0, s2>>>(dq_w2, K, H, D);
        xqtab_reduce_kernel<<<(K * D + 255) / 256, 256, 0, s2>>>(dq_b2, K, D);
        cudaEventRecord(eB, s2);
    }

    // ---- stream A: encoder chain ----
    {
        dim3 g1(KP1 / 128, (H + 31) / 32);
        transpose_split_kernel<<<g1, 256>>>(enc_w1, p_w1h, p_w1l, D, H, KP1, H);
    }
    {
        dim3 grid(1, B / 128, NSPLIT);
        mma_gemm_enc_kernel<<<grid, 256, SMEM_TOTAL>>>(
            x, p_w1h, p_w1l, p_part,
            /*lda=*/D, /*ldb=*/KP1, /*ldc=*/H, /*Nvalid=*/H, /*Dvalid=*/D,
            iPS, totalIters, /*splitStride=*/(long long)B * H);
    }
    fused_post_kernel<<<B / 16, 128>>>(enc_b1, enc_w2, enc_b2, emb, de_w1, de_b1,
                                       o_ze, o_zq, o_k, o_zd, o_dp,
                                       B, H, Z, K);

    // ---- stream A: decoder GEMM + fused x_q gather (joins stream B) ----
    cudaStreamWaitEvent(0, eB, 0);
    {
        dim3 grid(NT2, B / 128, 1);
        mma_gemm_dec_kernel<<<grid, 256, SMEM_TOTAL2>>>(
            p_hdh, p_hdl, p_w2e, de_b2, o_k, o_xe, o_xq,
            /*lda=*/H, /*ldb=*/H, /*ldc=*/D, /*Nvalid=*/D, /*iters=*/H / 32);
    }
}